// round 3
// baseline (speedup 1.0000x reference)
#include <cuda_runtime.h>
#include <math.h>

// ---------------- problem dims ----------------
#define D2 1024          // 2H
#define D4 2048          // 4H
#define G3 6144          // 3*D4
#define LL 64            // answer length
#define VV 32000         // vocab
#define HH 512           // H
#define NQ 32
#define NSUM 4128        // 32 + 4096

// ---------------- persistent kernel config ----------------
#define NB 148           // 1 CTA/SM resident (152-SM part idles 4 SMs; never deadlocks)
#define NT 256
#define NWARP 8
#define GWARPS (NB * NWARP)   // 1184

// ---------------- device scratch (static, no allocation) ----------------
__device__ __align__(16) float g_hpart[64 * D2];
__device__ __align__(16) float g_h[D2];
__device__ __align__(16) float g_uah[D2];
__device__ __align__(16) float g_d[2][D4];       // decoder state double buffer
__device__ __align__(16) float g_gh[G3];         // W_hh @ hprev + b_hh
__device__ __align__(16) float g_scon[2 * D2];   // score contributions v[j]*tanh(...)
__device__ __align__(16) float g_vt[D2];         // v_r @ hprev partials
__device__ __align__(16) float g_GIw[LL * G3];   // precomputed W_ih[:, :D2] @ w_t + b_ih
__device__ __align__(16) float g_RW[LL * D2];    // precomputed w_r @ w_t
__device__ __align__(16) float g_rpart[2][D2];   // RW[t] + u_r @ c   (parity-buffered)
__device__ __align__(16) float g_rt[LL * HH];    // maxout outputs (logits A operand)
__device__ __align__(16) float g_logits[LL * VV];
__device__ unsigned g_bar_cnt;                   // zero-init; returns to 0 each launch
__device__ unsigned g_bar_gen;                   // monotonic across graph replays

// ---------------- helpers ----------------
__device__ __forceinline__ float wred(float v) {
#pragma unroll
    for (int o = 16; o; o >>= 1) v += __shfl_xor_sync(0xffffffffu, v, o);
    return v;
}

template <int LEN>
__device__ __forceinline__ float warp_dot(const float* __restrict__ w,
                                          const float* __restrict__ v, int lane) {
    constexpr int NI = LEN / 128;
    float acc = 0.f;
#pragma unroll
    for (int i = 0; i < NI; ++i) {
        float4 a = *reinterpret_cast<const float4*>(w + i * 128 + lane * 4);
        float4 b = *reinterpret_cast<const float4*>(v + i * 128 + lane * 4);
        acc = fmaf(a.x, b.x, acc); acc = fmaf(a.y, b.y, acc);
        acc = fmaf(a.z, b.z, acc); acc = fmaf(a.w, b.w, acc);
    }
    return wred(acc);
}

// Replay-safe generation grid barrier. Each launch reads the persisted
// generation at entry (identical across CTAs: the previous launch fully
// completed). Releaser resets cnt before publishing gen; waiters fence after
// observing gen, so no atomicAdd for barrier G+1 can overlap the cnt reset.
__device__ __forceinline__ void gsync(unsigned gen) {
    __syncthreads();
    if (threadIdx.x == 0) {
        __threadfence();
        unsigned prev = atomicAdd(&g_bar_cnt, 1u);
        if (prev == NB - 1u) {
            g_bar_cnt = 0u;
            __threadfence();
            *(volatile unsigned*)&g_bar_gen = gen;
        } else {
            while ((int)(*(volatile unsigned*)&g_bar_gen - gen) < 0) __nanosleep(64);
            __threadfence();
        }
    }
    __syncthreads();
}

// packed fp32x2 FMA (Blackwell FFMA2 — only reachable via PTX)
#define FMA2(c, a, b) \
    asm("fma.rn.f32x2 %0, %1, %2, %0;" : "+l"(c) : "l"(a), "l"(b))

// ---------------- setup kernels ----------------
// partial column sums of [h_q; h_p] : 64 blocks x 65 rows
__global__ void k_colsum(const float* __restrict__ h_q, const float* __restrict__ h_p) {
    int b = blockIdx.x;
    int r0 = b * 65, r1 = min(r0 + 65, NSUM);
    int c = threadIdx.x;
    float acc[4] = {0.f, 0.f, 0.f, 0.f};
    for (int r = r0; r < r1; ++r) {
        const float* src = (r < NQ) ? (h_q + (size_t)r * D2) : (h_p + (size_t)(r - NQ) * D2);
#pragma unroll
        for (int i = 0; i < 4; ++i) acc[i] += src[c + i * 256];
    }
#pragma unroll
    for (int i = 0; i < 4; ++i) g_hpart[b * D2 + c + i * 256] = acc[i];
}

__global__ void k_finish_h() {
    int c = blockIdx.x * 256 + threadIdx.x;
    float s = 0.f;
#pragma unroll 8
    for (int b = 0; b < 64; ++b) s += g_hpart[b * D2 + c];
    g_h[c] = s;
}

// u_a_h = u_a @ h ; d0 = tanh(w_d @ [h_q0 ; h_p0] + b)
__global__ void k_rows(const float* __restrict__ u_a, const float* __restrict__ w_d,
                       const float* __restrict__ w_d_b,
                       const float* __restrict__ h_q, const float* __restrict__ h_p) {
    int warp = threadIdx.x >> 5, lane = threadIdx.x & 31;
    int row = blockIdx.x * 8 + warp;   // 384 blocks * 8 warps = 3072 tasks
    if (row < D2) {
        float dot = warp_dot<D2>(u_a + (size_t)row * D2, g_h, lane);
        if (lane == 0) g_uah[row] = dot;
    } else if (row < 2 * D2) {
        int j = row - D2;
        float dot = warp_dot<D2>(w_d + (size_t)j * D2, h_q, lane);
        if (lane == 0) g_d[0][j] = tanhf(dot + w_d_b[j]);
    } else {
        int j = row - 2 * D2;
        float dot = warp_dot<D2>(w_d + (size_t)j * D2, h_p, lane);
        if (lane == 0) g_d[0][D2 + j] = tanhf(dot + w_d_b[j]);
    }
}

// GIw[t][r] = W_ih[r, :D2] @ ans[t] + b_ih[r]  (rows 0..6143)
// RW [t][j] = w_r[j] @ ans[t]                  (rows 6144..7167)
__global__ void __launch_bounds__(256) k_gemm0(
    const float* __restrict__ w_ih, const float* __restrict__ w_r,
    const float* __restrict__ b_ih, const float* __restrict__ ans) {
    __shared__ __align__(16) float Wt[32][68];
    __shared__ __align__(16) float At[32][68];
    int rbase = blockIdx.x * 64;       // 112 blocks cover 7168 rows
    int tid = threadIdx.x;
    int rr = tid & 15, tt = tid >> 4;
    float acc[4][4];
#pragma unroll
    for (int i = 0; i < 4; ++i)
#pragma unroll
        for (int j = 0; j < 4; ++j) acc[i][j] = 0.f;

    for (int k0 = 0; k0 < D2; k0 += 32) {
        __syncthreads();
#pragma unroll
        for (int it = 0; it < 2; ++it) {
            int i = tid + it * 256;
            int r = i >> 3, k4 = (i & 7) * 4;
            int row = rbase + r;
            const float* src = (row < G3) ? (w_ih + (size_t)row * D4)
                                          : (w_r + (size_t)(row - G3) * D2);
            float4 v = *reinterpret_cast<const float4*>(src + k0 + k4);
            Wt[k4 + 0][r] = v.x; Wt[k4 + 1][r] = v.y;
            Wt[k4 + 2][r] = v.z; Wt[k4 + 3][r] = v.w;
        }
#pragma unroll
        for (int it = 0; it < 2; ++it) {
            int i = tid + it * 256;
            int t = i >> 3, k4 = (i & 7) * 4;
            float4 v = *reinterpret_cast<const float4*>(ans + (size_t)t * D2 + k0 + k4);
            At[k4 + 0][t] = v.x; At[k4 + 1][t] = v.y;
            At[k4 + 2][t] = v.z; At[k4 + 3][t] = v.w;
        }
        __syncthreads();
#pragma unroll
        for (int k = 0; k < 32; ++k) {
            float4 wv = *reinterpret_cast<const float4*>(&Wt[k][rr * 4]);
            float4 av = *reinterpret_cast<const float4*>(&At[k][tt * 4]);
            float wa[4] = {wv.x, wv.y, wv.z, wv.w};
            float aa[4] = {av.x, av.y, av.z, av.w};
#pragma unroll
            for (int i = 0; i < 4; ++i)
#pragma unroll
                for (int j = 0; j < 4; ++j)
                    acc[i][j] = fmaf(wa[i], aa[j], acc[i][j]);
        }
    }
#pragma unroll
    for (int i = 0; i < 4; ++i) {
        int row = rbase + rr * 4 + i;
        float b = (row < G3) ? b_ih[row] : 0.f;
#pragma unroll
        for (int j = 0; j < 4; ++j) {
            int t = tt * 4 + j;
            float v = acc[i][j] + b;
            if (row < G3) g_GIw[(size_t)t * G3 + row] = v;
            else          g_RW[(size_t)t * D2 + (row - G3)] = v;
        }
    }
}

// ---------------- persistent recurrence kernel ----------------
__global__ void __launch_bounds__(NT, 1) k_persist(
    const float* __restrict__ v_w, const float* __restrict__ w_a,
    const float* __restrict__ u_r, const float* __restrict__ v_r,
    const float* __restrict__ w_ih, const float* __restrict__ w_hh,
    const float* __restrict__ b_hh) {
    const int tid = threadIdx.x;
    const int wid = tid >> 5, lane = tid & 31;
    const int gw = blockIdx.x * NWARP + wid;
    __shared__ __align__(16) float sh_h[D4];   // hprev broadcast (8KB)
    __shared__ float sred0[NT];
    __shared__ float sred1[NT];
    __shared__ float s_a[2];
    __shared__ unsigned s_gen;

    if (tid == 0) s_gen = *(volatile unsigned*)&g_bar_gen;
    __syncthreads();
    unsigned gen = s_gen;

    float4 h4[16];   // register cache of hprev slice: (i*128 + lane*4 + c)
    float4 c4[8];    // register cache of context c slice (length D2)

    for (int t = 0; t < LL; ++t) {
        const int cur = t & 1, nxt = cur ^ 1;
        // broadcast hprev into smem once per CTA
        {
            const float4* src = reinterpret_cast<const float4*>(g_d[cur]);
            float4* dst = reinterpret_cast<float4*>(sh_h);
            dst[tid] = src[tid];
            dst[tid + 256] = src[tid + 256];
        }
        __syncthreads();
#pragma unroll
        for (int i = 0; i < 16; ++i)
            h4[i] = *reinterpret_cast<const float4*>(sh_h + i * 128 + lane * 4);

        // ---------------- phase A ----------------
        // ids: [0,6144) gh rows (8KB) | [6144,7168) v_r rows (8KB)
        //      [7168,8192) attention rows (4KB, 2 accumulators)
        for (int id = gw; id < 8192; id += GWARPS) {
            if (id < 6144) {
                int r = id;
                const float* W = w_hh + (size_t)r * D4 + lane * 4;
                float a0 = 0.f, a1 = 0.f;
#pragma unroll
                for (int i = 0; i < 16; i += 2) {
                    float4 w0 = *reinterpret_cast<const float4*>(W + i * 128);
                    float4 w1 = *reinterpret_cast<const float4*>(W + (i + 1) * 128);
                    a0 = fmaf(w0.x, h4[i].x, a0); a0 = fmaf(w0.y, h4[i].y, a0);
                    a0 = fmaf(w0.z, h4[i].z, a0); a0 = fmaf(w0.w, h4[i].w, a0);
                    a1 = fmaf(w1.x, h4[i + 1].x, a1); a1 = fmaf(w1.y, h4[i + 1].y, a1);
                    a1 = fmaf(w1.z, h4[i + 1].z, a1); a1 = fmaf(w1.w, h4[i + 1].w, a1);
                }
                float dot = wred(a0 + a1);
                if (lane == 0) g_gh[r] = dot + b_hh[r];
            } else if (id < 7168) {
                int j = id - 6144;     // 0..1023
                const float* W = v_r + (size_t)j * D4 + lane * 4;
                float a0 = 0.f, a1 = 0.f;
#pragma unroll
                for (int i = 0; i < 16; i += 2) {
                    float4 w0 = *reinterpret_cast<const float4*>(W + i * 128);
                    float4 w1 = *reinterpret_cast<const float4*>(W + (i + 1) * 128);
                    a0 = fmaf(w0.x, h4[i].x, a0); a0 = fmaf(w0.y, h4[i].y, a0);
                    a0 = fmaf(w0.z, h4[i].z, a0); a0 = fmaf(w0.w, h4[i].w, a0);
                    a1 = fmaf(w1.x, h4[i + 1].x, a1); a1 = fmaf(w1.y, h4[i + 1].y, a1);
                    a1 = fmaf(w1.z, h4[i + 1].z, a1); a1 = fmaf(w1.w, h4[i + 1].w, a1);
                }
                float dot = wred(a0 + a1);
                if (lane == 0) g_vt[j] = dot;
            } else {
                int j = id - 7168;     // 0..1023 : both d-rows share the W row
                const float* W = w_a + (size_t)j * D2 + lane * 4;
                float a0 = 0.f, a1 = 0.f;
#pragma unroll
                for (int c = 0; c < 8; ++c) {
                    float4 w = *reinterpret_cast<const float4*>(W + c * 128);
                    a0 = fmaf(w.x, h4[c].x, a0); a0 = fmaf(w.y, h4[c].y, a0);
                    a0 = fmaf(w.z, h4[c].z, a0); a0 = fmaf(w.w, h4[c].w, a0);
                    const float4 h = h4[8 + c];
                    a1 = fmaf(w.x, h.x, a1); a1 = fmaf(w.y, h.y, a1);
                    a1 = fmaf(w.z, h.z, a1); a1 = fmaf(w.w, h.w, a1);
                }
                a0 = wred(a0); a1 = wred(a1);
                if (lane == 0) {
                    float vj = v_w[j], uj = g_uah[j];
                    g_scon[j]      = vj * tanhf(a0 + uj);
                    g_scon[D2 + j] = vj * tanhf(a1 + uj);
                }
            }
        }
        ++gen; gsync(gen);

        // ---------------- phase B preamble: scores -> a -> c (registers) ----
        {
            float p0 = 0.f, p1 = 0.f;
#pragma unroll
            for (int kk = 0; kk < 4; ++kk) {
                p0 += g_scon[tid + kk * 256];
                p1 += g_scon[D2 + tid + kk * 256];
            }
            sred0[tid] = p0; sred1[tid] = p1;
            __syncthreads();
            for (int s = 128; s; s >>= 1) {
                if (tid < s) { sred0[tid] += sred0[tid + s]; sred1[tid] += sred1[tid + s]; }
                __syncthreads();
            }
            if (tid == 0) {
                float s0 = sred0[0], s1 = sred1[0];
                float m = fmaxf(s0, s1);
                float e0 = expf(s0 - m), e1 = expf(s1 - m);
                float inv = 1.f / (e0 + e1);
                s_a[0] = e0 * inv; s_a[1] = e1 * inv;
            }
            __syncthreads();
            float a0 = s_a[0], a1 = s_a[1];
#pragma unroll
            for (int c = 0; c < 8; ++c) {
                c4[c].x = a0 * h4[c].x + a1 * h4[8 + c].x;
                c4[c].y = a0 * h4[c].y + a1 * h4[8 + c].y;
                c4[c].z = a0 * h4[c].z + a1 * h4[8 + c].z;
                c4[c].w = a0 * h4[c].w + a1 * h4[8 + c].w;
            }
        }

        // ---------------- phase B ----------------
        // ids: [0,2048) GRU lane k | [2048,3072) u_r rows | [3072,3088) maxout finalize
        for (int id = gw; id < 3088; id += GWARPS) {
            if (id < D4) {
                int k = id;
                const float* Wr = w_ih + (size_t)k * D4 + D2 + lane * 4;
                const float* Wz = w_ih + (size_t)(k + D4) * D4 + D2 + lane * 4;
                const float* Wn = w_ih + (size_t)(k + 2 * D4) * D4 + D2 + lane * 4;
                float ar = 0.f, az = 0.f, an = 0.f;
#pragma unroll
                for (int c = 0; c < 8; ++c) {
                    float4 wr_ = *reinterpret_cast<const float4*>(Wr + c * 128);
                    float4 wz_ = *reinterpret_cast<const float4*>(Wz + c * 128);
                    float4 wn_ = *reinterpret_cast<const float4*>(Wn + c * 128);
                    ar = fmaf(wr_.x, c4[c].x, ar); ar = fmaf(wr_.y, c4[c].y, ar);
                    ar = fmaf(wr_.z, c4[c].z, ar); ar = fmaf(wr_.w, c4[c].w, ar);
                    az = fmaf(wz_.x, c4[c].x, az); az = fmaf(wz_.y, c4[c].y, az);
                    az = fmaf(wz_.z, c4[c].z, az); az = fmaf(wz_.w, c4[c].w, az);
                    an = fmaf(wn_.x, c4[c].x, an); an = fmaf(wn_.y, c4[c].y, an);
                    an = fmaf(wn_.z, c4[c].z, an); an = fmaf(wn_.w, c4[c].w, an);
                }
                ar = wred(ar); az = wred(az); an = wred(an);
                if (lane == 0) {
                    const float* gi = g_GIw + (size_t)t * G3;
                    float rg = 1.f / (1.f + expf(-(gi[k]          + ar + g_gh[k])));
                    float zg = 1.f / (1.f + expf(-(gi[k + D4]     + az + g_gh[k + D4])));
                    float ng = tanhf(gi[k + 2 * D4] + an + rg * g_gh[k + 2 * D4]);
                    g_d[nxt][k] = (1.f - zg) * ng + zg * sh_h[k];
                }
            } else if (id < 3072) {
                int j = id - D4;       // 0..1023
                const float* W = u_r + (size_t)j * D2 + lane * 4;
                float a0 = 0.f;
#pragma unroll
                for (int c = 0; c < 8; ++c) {
                    float4 w = *reinterpret_cast<const float4*>(W + c * 128);
                    a0 = fmaf(w.x, c4[c].x, a0); a0 = fmaf(w.y, c4[c].y, a0);
                    a0 = fmaf(w.z, c4[c].z, a0); a0 = fmaf(w.w, c4[c].w, a0);
                }
                a0 = wred(a0);
                if (lane == 0)
                    g_rpart[cur][j] = g_RW[(size_t)t * D2 + j] + a0;
            } else {
                if (t > 0) {           // finalize r_{t-1}: 16 tasks x 32 lanes
                    int j = (id - 3072) * 32 + lane;   // 0..511
                    float f0 = g_rpart[nxt][j]      + g_vt[j];
                    float f1 = g_rpart[nxt][j + HH] + g_vt[j + HH];
                    g_rt[(size_t)(t - 1) * HH + j] = fmaxf(f0, f1);
                }
            }
        }
        ++gen; gsync(gen);
    }

    // ---------------- epilogue: finalize r_t for t=63 (h_new in g_d[0]) ----
    {
        const float4* src = reinterpret_cast<const float4*>(g_d[0]);
        float4* dst = reinterpret_cast<float4*>(sh_h);
        dst[tid] = src[tid];
        dst[tid + 256] = src[tid + 256];
        __syncthreads();
#pragma unroll
        for (int i = 0; i < 16; ++i)
            h4[i] = *reinterpret_cast<const float4*>(sh_h + i * 128 + lane * 4);
        for (int id = gw; id < 1024; id += GWARPS) {
            const float* W = v_r + (size_t)id * D4 + lane * 4;
            float a0 = 0.f, a1 = 0.f;
#pragma unroll
            for (int i = 0; i < 16; i += 2) {
                float4 w0 = *reinterpret_cast<const float4*>(W + i * 128);
                float4 w1 = *reinterpret_cast<const float4*>(W + (i + 1) * 128);
                a0 = fmaf(w0.x, h4[i].x, a0); a0 = fmaf(w0.y, h4[i].y, a0);
                a0 = fmaf(w0.z, h4[i].z, a0); a0 = fmaf(w0.w, h4[i].w, a0);
                a1 = fmaf(w1.x, h4[i + 1].x, a1); a1 = fmaf(w1.y, h4[i + 1].y, a1);
                a1 = fmaf(w1.z, h4[i + 1].z, a1); a1 = fmaf(w1.w, h4[i + 1].w, a1);
            }
            float dot = wred(a0 + a1);
            if (lane == 0) g_vt[id] = dot;
        }
        ++gen; gsync(gen);
        if (gw < 16) {                 // t=63 wrote g_rpart[1]
            int j = gw * 32 + lane;
            float f0 = g_rpart[1][j]      + g_vt[j];
            float f1 = g_rpart[1][j + HH] + g_vt[j + HH];
            g_rt[(size_t)63 * HH + j] = fmaxf(f0, f1);
        }
    }
}

// ---------------- logits GEMM: (64 x 512) @ wo^T (512 x 32000) ----------
// FFMA2 path: A tile stored duplicated so packed operands come straight
// from LDS.128, B pairs are naturally consecutive.
__global__ void __launch_bounds__(256) k_logits(const float* __restrict__ wo) {
    __shared__ __align__(16) float At2[32][144];  // At2[k][2m] = At2[k][2m+1] = A[m][k]
    __shared__ __align__(16) float Bt[32][136];   // Bt[k][n]
    const int tid = threadIdx.x;
    const int v0 = blockIdx.x * 128;              // 250 blocks
    const int tm = tid & 15, tn = tid >> 4;
    unsigned long long acc[4][4];                 // [m][j-pair] packed f32x2
#pragma unroll
    for (int i = 0; i < 4; ++i)
#pragma unroll
        for (int j = 0; j < 4; ++j) acc[i][j] = 0ull;

    for (int k0 = 0; k0 < HH; k0 += 32) {
        __syncthreads();
#pragma unroll
        for (int it = 0; it < 2; ++it) {          // 64x32 A tile, duplicated
            int i = tid + it * 256;
            int m = i >> 3, k4 = (i & 7) * 4;
            float4 v = *reinterpret_cast<const float4*>(g_rt + (size_t)m * HH + k0 + k4);
            At2[k4 + 0][2 * m] = v.x; At2[k4 + 0][2 * m + 1] = v.x;
            At2[k4 + 1][2 * m] = v.y; At2[k4 + 1][2 * m + 1] = v.y;
            At2[k4 + 2][2 * m] = v.z; At2[k4 + 2][2 * m + 1] = v.z;
            At2[k4 + 3][2 * m] = v.w; At2[k4 + 3][2 * m + 1] = v.w;
        }
#pragma unroll
        for (int it = 0; it < 4; ++it) {          // 128x32 B tile
            int i = tid + it * 256;
            int n = i >> 3, k4 = (i & 7) * 4;
            float4 v = *reinterpret_cast<const float4*>(wo + (size_t)(v0 + n) * HH + k0 + k4);
            Bt[k4 + 0][n] = v.x; Bt[k4 + 1][n] = v.y;
            Bt[k4 + 2][n] = v.z; Bt[k4 + 3][n] = v.w;
        }
        __syncthreads();
#pragma unroll
        for (int k = 0; k < 32; ++k) {
            ulonglong2 aA = *reinterpret_cast<const ulonglong2*>(&At2[k][tm * 8]);
            ulonglong2 aB = *reinterpret_cast<const ulonglong2*>(&At2[k][tm * 8 + 4]);
            ulonglong2 b0 = *reinterpret_cast<const ulonglong2*>(&Bt[k][tn * 8]);
            ulonglong2 b1 = *reinterpret_cast<const ulonglong2*>(&Bt[k][tn * 8 + 4]);
            FMA2(acc[0][0], aA.x, b0.x); FMA2(acc[0][1], aA.x, b0.y);
            FMA2(acc[0][2], aA.x, b1.x); FMA2(acc[0][3], aA.x, b1.y);
            FMA2(acc[1][0], aA.y, b0.x); FMA2(acc[1][1], aA.y, b0.y);
            FMA2(acc[1][2], aA.y, b1.x); FMA2(acc[1][3], aA.y, b1.y);
            FMA2(acc[2][0], aB.x, b0.x); FMA2(acc[2][1], aB.x, b0.y);
            FMA2(acc[2][2], aB.x, b1.x); FMA2(acc[2][3], aB.x, b1.y);
            FMA2(acc[3][0], aB.y, b0.x); FMA2(acc[3][1], aB.y, b0.y);
            FMA2(acc[3][2], aB.y, b1.x); FMA2(acc[3][3], aB.y, b1.y);
        }
    }
#pragma unroll
    for (int i = 0; i < 4; ++i) {
        float lo[4], hi[4];
#pragma unroll
        for (int j = 0; j < 4; ++j)
            asm("mov.b64 {%0, %1}, %2;" : "=f"(lo[j]), "=f"(hi[j]) : "l"(acc[i][j]));
        float* dst = g_logits + (size_t)(tm * 4 + i) * VV + v0 + tn * 8;
        *reinterpret_cast<float4*>(dst)     = make_float4(lo[0], hi[0], lo[1], hi[1]);
        *reinterpret_cast<float4*>(dst + 4) = make_float4(lo[2], hi[2], lo[3], hi[3]);
    }
}

// ---------------- row softmax over vocab -> d_out ----------------
__global__ void __launch_bounds__(512) k_softmax(float* __restrict__ out) {
    __shared__ float sh[512];
    const int row = blockIdx.x, tid = threadIdx.x;
    const float* lg = g_logits + (size_t)row * VV;
    float m = -INFINITY;
    for (int i = tid; i < VV; i += 512) m = fmaxf(m, lg[i]);
    sh[tid] = m; __syncthreads();
    for (int s = 256; s; s >>= 1) { if (tid < s) sh[tid] = fmaxf(sh[tid], sh[tid + s]); __syncthreads(); }
    m = sh[0]; __syncthreads();
    float sum = 0.f;
    for (int i = tid; i < VV; i += 512) sum += expf(lg[i] - m);
    sh[tid] = sum; __syncthreads();
    for (int s = 256; s; s >>= 1) { if (tid < s) sh[tid] += sh[tid + s]; __syncthreads(); }
    float inv = 1.f / sh[0];
    float* o = out + (size_t)row * VV;
    for (int i = tid; i < VV; i += 512) o[i] = expf(lg[i] - m) * inv;
}

// ---------------- launch ----------------
extern "C" void kernel_launch(void* const* d_in, const int* in_sizes, int n_in,
                              void* d_out, int out_size) {
    (void)in_sizes; (void)n_in; (void)out_size;
    const float* h_q    = (const float*)d_in[0];
    const float* h_p    = (const float*)d_in[1];
    const float* ans    = (const float*)d_in[2];
    const float* v_w    = (const float*)d_in[3];
    const float* w_d_w  = (const float*)d_in[4];
    const float* w_d_b  = (const float*)d_in[5];
    const float* w_a_w  = (const float*)d_in[6];
    const float* u_a_w  = (const float*)d_in[7];
    const float* w_r_w  = (const float*)d_in[8];
    const float* u_r_w  = (const float*)d_in[9];
    const float* v_r_w  = (const float*)d_in[10];
    const float* w_o_w  = (const float*)d_in[11];
    const float* gw_ih  = (const float*)d_in[12];
    const float* gw_hh  = (const float*)d_in[13];
    const float* gb_ih  = (const float*)d_in[14];
    const float* gb_hh  = (const float*)d_in[15];
    float* out = (float*)d_out;

    k_colsum<<<64, 256>>>(h_q, h_p);
    k_finish_h<<<4, 256>>>();
    k_rows<<<384, 256>>>(u_a_w, w_d_w, w_d_b, h_q, h_p);
    k_gemm0<<<112, 256>>>(gw_ih, w_r_w, gb_ih, ans);
    k_persist<<<NB, NT>>>(v_w, w_a_w, u_r_w, v_r_w, gw_ih, gw_hh, gb_hh);
    k_logits<<<VV / 128, 256>>>(w_o_w);
    k_softmax<<<LL, 512>>>(out);
}

// round 9
// speedup vs baseline: 1.1661x; 1.1661x over previous
#include <cuda_runtime.h>
#include <cuda_fp16.h>
#include <math.h>

// ---------------- problem dims ----------------
#define D2 1024          // 2H
#define D4 2048          // 4H
#define G3 6144          // 3*D4
#define LL 64            // answer length
#define VV 32000         // vocab
#define HH 512           // H
#define NQ 32
#define NSUM 4128        // 32 + 4096

// ---------------- persistent kernel config ----------------
#define NB 148           // 1 CTA/SM resident (152-SM part idles 4 SMs; never deadlocks)
#define NT 256
#define NWARP 8
#define GWARPS (NB * NWARP)   // 1184

// ---------------- device scratch (static, no allocation) ----------------
__device__ __align__(16) float g_hpart[64 * D2];
__device__ __align__(16) float g_h[D2];
__device__ __align__(16) float g_uah[D2];
__device__ __align__(16) float g_d[2][D4];       // decoder state double buffer
__device__ __align__(16) float g_gh[G3];         // W_hh @ hprev + b_hh
__device__ __align__(16) float g_scon[2 * D2];   // score contributions v[j]*tanh(...)
__device__ __align__(16) float g_vt[D2];         // v_r @ hprev partials
__device__ __align__(16) float g_GIw[LL * G3];   // precomputed W_ih[:, :D2] @ w_t + b_ih
__device__ __align__(16) float g_RW[LL * D2];    // precomputed w_r @ w_t
__device__ __align__(16) float g_rpart[2][D2];   // RW[t] + u_r @ c   (parity-buffered)
__device__ __align__(16) float g_rt[LL * HH];    // maxout outputs (logits A operand)
__device__ __align__(16) float g_logits[LL * VV];
__device__ unsigned g_bar_cnt;                   // zero-init; returns to 0 each launch
__device__ unsigned g_bar_gen;                   // monotonic across graph replays

// fp16 copies of the loop-resident weight matrices (~46 MB total)
__device__ __align__(16) __half g_whh_h[G3 * D4];    // 25.2 MB
__device__ __align__(16) __half g_wihc_h[G3 * D2];   // 12.6 MB (c-half of W_ih, compact)
__device__ __align__(16) __half g_vr_h[D2 * D4];     //  4.2 MB
__device__ __align__(16) __half g_ur_h[D2 * D2];     //  2.1 MB
__device__ __align__(16) __half g_wa_h[D2 * D2];     //  2.1 MB

// ---------------- helpers ----------------
__device__ __forceinline__ float wred(float v) {
#pragma unroll
    for (int o = 16; o; o >>= 1) v += __shfl_xor_sync(0xffffffffu, v, o);
    return v;
}

template <int LEN>
__device__ __forceinline__ float warp_dot(const float* __restrict__ w,
                                          const float* __restrict__ v, int lane) {
    constexpr int NI = LEN / 128;
    float acc = 0.f;
#pragma unroll
    for (int i = 0; i < NI; ++i) {
        float4 a = *reinterpret_cast<const float4*>(w + i * 128 + lane * 4);
        float4 b = *reinterpret_cast<const float4*>(v + i * 128 + lane * 4);
        acc = fmaf(a.x, b.x, acc); acc = fmaf(a.y, b.y, acc);
        acc = fmaf(a.z, b.z, acc); acc = fmaf(a.w, b.w, acc);
    }
    return wred(acc);
}

// Replay-safe generation grid barrier (validated in the R3 passing run).
__device__ __forceinline__ void gsync(unsigned gen) {
    __syncthreads();
    if (threadIdx.x == 0) {
        __threadfence();
        unsigned prev = atomicAdd(&g_bar_cnt, 1u);
        if (prev == NB - 1u) {
            g_bar_cnt = 0u;
            __threadfence();
            *(volatile unsigned*)&g_bar_gen = gen;
        } else {
            while ((int)(*(volatile unsigned*)&g_bar_gen - gen) < 0) __nanosleep(64);
            __threadfence();
        }
    }
    __syncthreads();
}

// packed fp32x2 FMA (Blackwell FFMA2 — only reachable via PTX)
#define FMA2(c, a, b) \
    asm("fma.rn.f32x2 %0, %1, %2, %0;" : "+l"(c) : "l"(a), "l"(b))

// fma of 8 fp16 weights (as uint4) against two float4 halves of the vector
#define FMA_H8(raw, va, vb, acc0, acc1) do {                                   \
    const __half2* _hp = reinterpret_cast<const __half2*>(&(raw));             \
    float2 _w0 = __half22float2(_hp[0]); float2 _w1 = __half22float2(_hp[1]);  \
    float2 _w2 = __half22float2(_hp[2]); float2 _w3 = __half22float2(_hp[3]);  \
    acc0 = fmaf(_w0.x, (va).x, acc0); acc0 = fmaf(_w0.y, (va).y, acc0);        \
    acc0 = fmaf(_w1.x, (va).z, acc0); acc0 = fmaf(_w1.y, (va).w, acc0);        \
    acc1 = fmaf(_w2.x, (vb).x, acc1); acc1 = fmaf(_w2.y, (vb).y, acc1);        \
    acc1 = fmaf(_w3.x, (vb).z, acc1); acc1 = fmaf(_w3.y, (vb).w, acc1);        \
} while (0)

// ---------------- weight conversion kernels ----------------
// contiguous fp32 -> fp16 for W_hh, v_r, u_r, w_a laid out back-to-back
__global__ void k_conv4(const float* __restrict__ whh, const float* __restrict__ vr,
                        const float* __restrict__ ur, const float* __restrict__ wa) {
    const int n_whh = G3 * D4 / 4, n_vr = D2 * D4 / 4, n_ur = D2 * D2 / 4, n_wa = D2 * D2 / 4;
    int i = blockIdx.x * blockDim.x + threadIdx.x;
    const float* src; __half* dst; int off;
    if (i < n_whh)                            { src = whh; dst = g_whh_h; off = i; }
    else if ((i -= n_whh) < n_vr)             { src = vr;  dst = g_vr_h;  off = i; }
    else if ((i -= n_vr) < n_ur)              { src = ur;  dst = g_ur_h;  off = i; }
    else if ((i -= n_ur) < n_wa)              { src = wa;  dst = g_wa_h;  off = i; }
    else return;
    float4 v = reinterpret_cast<const float4*>(src)[off];
    __half2 h0 = __floats2half2_rn(v.x, v.y);
    __half2 h1 = __floats2half2_rn(v.z, v.w);
    reinterpret_cast<__half2*>(dst)[2 * off]     = h0;
    reinterpret_cast<__half2*>(dst)[2 * off + 1] = h1;
}

// strided: extract the c-half of W_ih into a compact fp16 matrix
__global__ void k_conv_wihc(const float* __restrict__ w_ih) {
    int i = blockIdx.x * blockDim.x + threadIdx.x;   // over G3 * D2/4
    if (i < G3 * (D2 / 4)) {
        int r = i / (D2 / 4), c4 = (i % (D2 / 4)) * 4;
        float4 v = *reinterpret_cast<const float4*>(w_ih + (size_t)r * D4 + D2 + c4);
        __half2 h0 = __floats2half2_rn(v.x, v.y);
        __half2 h1 = __floats2half2_rn(v.z, v.w);
        __half2* dst = reinterpret_cast<__half2*>(g_wihc_h + (size_t)r * D2 + c4);
        dst[0] = h0; dst[1] = h1;
    }
}

// ---------------- setup kernels ----------------
__global__ void k_colsum(const float* __restrict__ h_q, const float* __restrict__ h_p) {
    int b = blockIdx.x;
    int r0 = b * 65, r1 = min(r0 + 65, NSUM);
    int c = threadIdx.x;
    float acc[4] = {0.f, 0.f, 0.f, 0.f};
    for (int r = r0; r < r1; ++r) {
        const float* src = (r < NQ) ? (h_q + (size_t)r * D2) : (h_p + (size_t)(r - NQ) * D2);
#pragma unroll
        for (int i = 0; i < 4; ++i) acc[i] += src[c + i * 256];
    }
#pragma unroll
    for (int i = 0; i < 4; ++i) g_hpart[b * D2 + c + i * 256] = acc[i];
}

__global__ void k_finish_h() {
    int c = blockIdx.x * 256 + threadIdx.x;
    float s = 0.f;
#pragma unroll 8
    for (int b = 0; b < 64; ++b) s += g_hpart[b * D2 + c];
    g_h[c] = s;
}

__global__ void k_rows(const float* __restrict__ u_a, const float* __restrict__ w_d,
                       const float* __restrict__ w_d_b,
                       const float* __restrict__ h_q, const float* __restrict__ h_p) {
    int warp = threadIdx.x >> 5, lane = threadIdx.x & 31;
    int row = blockIdx.x * 8 + warp;
    if (row < D2) {
        float dot = warp_dot<D2>(u_a + (size_t)row * D2, g_h, lane);
        if (lane == 0) g_uah[row] = dot;
    } else if (row < 2 * D2) {
        int j = row - D2;
        float dot = warp_dot<D2>(w_d + (size_t)j * D2, h_q, lane);
        if (lane == 0) g_d[0][j] = tanhf(dot + w_d_b[j]);
    } else {
        int j = row - 2 * D2;
        float dot = warp_dot<D2>(w_d + (size_t)j * D2, h_p, lane);
        if (lane == 0) g_d[0][D2 + j] = tanhf(dot + w_d_b[j]);
    }
}

// GIw[t][r] = W_ih[r, :D2] @ ans[t] + b_ih[r]  (rows 0..6143)
// RW [t][j] = w_r[j] @ ans[t]                  (rows 6144..7167)
__global__ void __launch_bounds__(256) k_gemm0(
    const float* __restrict__ w_ih, const float* __restrict__ w_r,
    const float* __restrict__ b_ih, const float* __restrict__ ans) {
    __shared__ __align__(16) float Wt[32][68];
    __shared__ __align__(16) float At[32][68];
    int rbase = blockIdx.x * 64;
    int tid = threadIdx.x;
    int rr = tid & 15, tt = tid >> 4;
    float acc[4][4];
#pragma unroll
    for (int i = 0; i < 4; ++i)
#pragma unroll
        for (int j = 0; j < 4; ++j) acc[i][j] = 0.f;

    for (int k0 = 0; k0 < D2; k0 += 32) {
        __syncthreads();
#pragma unroll
        for (int it = 0; it < 2; ++it) {
            int i = tid + it * 256;
            int r = i >> 3, k4 = (i & 7) * 4;
            int row = rbase + r;
            const float* src = (row < G3) ? (w_ih + (size_t)row * D4)
                                          : (w_r + (size_t)(row - G3) * D2);
            float4 v = *reinterpret_cast<const float4*>(src + k0 + k4);
            Wt[k4 + 0][r] = v.x; Wt[k4 + 1][r] = v.y;
            Wt[k4 + 2][r] = v.z; Wt[k4 + 3][r] = v.w;
        }
#pragma unroll
        for (int it = 0; it < 2; ++it) {
            int i = tid + it * 256;
            int t = i >> 3, k4 = (i & 7) * 4;
            float4 v = *reinterpret_cast<const float4*>(ans + (size_t)t * D2 + k0 + k4);
            At[k4 + 0][t] = v.x; At[k4 + 1][t] = v.y;
            At[k4 + 2][t] = v.z; At[k4 + 3][t] = v.w;
        }
        __syncthreads();
#pragma unroll
        for (int k = 0; k < 32; ++k) {
            float4 wv = *reinterpret_cast<const float4*>(&Wt[k][rr * 4]);
            float4 av = *reinterpret_cast<const float4*>(&At[k][tt * 4]);
            float wa[4] = {wv.x, wv.y, wv.z, wv.w};
            float aa[4] = {av.x, av.y, av.z, av.w};
#pragma unroll
            for (int i = 0; i < 4; ++i)
#pragma unroll
                for (int j = 0; j < 4; ++j)
                    acc[i][j] = fmaf(wa[i], aa[j], acc[i][j]);
        }
    }
#pragma unroll
    for (int i = 0; i < 4; ++i) {
        int row = rbase + rr * 4 + i;
        float b = (row < G3) ? b_ih[row] : 0.f;
#pragma unroll
        for (int j = 0; j < 4; ++j) {
            int t = tt * 4 + j;
            float v = acc[i][j] + b;
            if (row < G3) g_GIw[(size_t)t * G3 + row] = v;
            else          g_RW[(size_t)t * D2 + (row - G3)] = v;
        }
    }
}

// ---------------- persistent recurrence kernel (fp16 weight stream) --------
__global__ void __launch_bounds__(NT, 1) k_persist(
    const float* __restrict__ v_w, const float* __restrict__ b_hh) {
    const int tid = threadIdx.x;
    const int wid = tid >> 5, lane = tid & 31;
    const int gw = blockIdx.x * NWARP + wid;
    __shared__ __align__(16) float sh_h[D4];   // hprev broadcast (8KB)
    __shared__ float sred0[NT];
    __shared__ float sred1[NT];
    __shared__ float s_a[2];
    __shared__ unsigned s_gen;

    if (tid == 0) s_gen = *(volatile unsigned*)&g_bar_gen;
    __syncthreads();
    unsigned gen = s_gen;

    // lane slicing: chunk i covers vector elements [i*256 + lane*8, +8)
    float4 hA[8], hB[8];   // hprev slice (D4)
    float4 cA[4], cB[4];   // context slice (D2)

    for (int t = 0; t < LL; ++t) {
        const int cur = t & 1, nxt = cur ^ 1;
        {
            const float4* src = reinterpret_cast<const float4*>(g_d[cur]);
            float4* dst = reinterpret_cast<float4*>(sh_h);
            dst[tid] = src[tid];
            dst[tid + 256] = src[tid + 256];
        }
        __syncthreads();
#pragma unroll
        for (int i = 0; i < 8; ++i) {
            hA[i] = *reinterpret_cast<const float4*>(sh_h + i * 256 + lane * 8);
            hB[i] = *reinterpret_cast<const float4*>(sh_h + i * 256 + lane * 8 + 4);
        }

        // ---------------- phase A ----------------
        // ids: [0,6144) W_hh rows (4KB) | [6144,7168) v_r rows (4KB)
        //      [7168,8192) attention rows (2KB, both d-rows share the weight row)
        for (int id = gw; id < 8192; id += GWARPS) {
            if (id < 6144) {
                int r = id;
                const uint4* W4 = reinterpret_cast<const uint4*>(g_whh_h + (size_t)r * D4) + lane;
                float a0 = 0.f, a1 = 0.f;
#pragma unroll
                for (int i = 0; i < 8; ++i) {
                    uint4 raw = W4[i * 32];
                    FMA_H8(raw, hA[i], hB[i], a0, a1);
                }
                float dot = wred(a0 + a1);
                if (lane == 0) g_gh[r] = dot + b_hh[r];
            } else if (id < 7168) {
                int j = id - 6144;
                const uint4* W4 = reinterpret_cast<const uint4*>(g_vr_h + (size_t)j * D4) + lane;
                float a0 = 0.f, a1 = 0.f;
#pragma unroll
                for (int i = 0; i < 8; ++i) {
                    uint4 raw = W4[i * 32];
                    FMA_H8(raw, hA[i], hB[i], a0, a1);
                }
                float dot = wred(a0 + a1);
                if (lane == 0) g_vt[j] = dot;
            } else {
                int j = id - 7168;
                const uint4* W4 = reinterpret_cast<const uint4*>(g_wa_h + (size_t)j * D2) + lane;
                float s0a = 0.f, s0b = 0.f, s1a = 0.f, s1b = 0.f;
#pragma unroll
                for (int i = 0; i < 4; ++i) {
                    uint4 raw = W4[i * 32];
                    const __half2* hp = reinterpret_cast<const __half2*>(&raw);
                    float2 w0 = __half22float2(hp[0]); float2 w1 = __half22float2(hp[1]);
                    float2 w2 = __half22float2(hp[2]); float2 w3 = __half22float2(hp[3]);
                    // first d-row: h[0:1024) -> chunks i
                    s0a = fmaf(w0.x, hA[i].x, s0a); s0a = fmaf(w0.y, hA[i].y, s0a);
                    s0a = fmaf(w1.x, hA[i].z, s0a); s0a = fmaf(w1.y, hA[i].w, s0a);
                    s0b = fmaf(w2.x, hB[i].x, s0b); s0b = fmaf(w2.y, hB[i].y, s0b);
                    s0b = fmaf(w3.x, hB[i].z, s0b); s0b = fmaf(w3.y, hB[i].w, s0b);
                    // second d-row: h[1024:2048) -> chunks i+4
                    s1a = fmaf(w0.x, hA[i + 4].x, s1a); s1a = fmaf(w0.y, hA[i + 4].y, s1a);
                    s1a = fmaf(w1.x, hA[i + 4].z, s1a); s1a = fmaf(w1.y, hA[i + 4].w, s1a);
                    s1b = fmaf(w2.x, hB[i + 4].x, s1b); s1b = fmaf(w2.y, hB[i + 4].y, s1b);
                    s1b = fmaf(w3.x, hB[i + 4].z, s1b); s1b = fmaf(w3.y, hB[i + 4].w, s1b);
                }
                float a0 = wred(s0a + s0b);
                float a1 = wred(s1a + s1b);
                if (lane == 0) {
                    float vj = v_w[j], uj = g_uah[j];
                    g_scon[j]      = vj * tanhf(a0 + uj);
                    g_scon[D2 + j] = vj * tanhf(a1 + uj);
                }
            }
        }
        ++gen; gsync(gen);

        // ---------------- phase B preamble: scores -> a -> c (registers) ----
        {
            float p0 = 0.f, p1 = 0.f;
#pragma unroll
            for (int kk = 0; kk < 4; ++kk) {
                p0 += g_scon[tid + kk * 256];
                p1 += g_scon[D2 + tid + kk * 256];
            }
            sred0[tid] = p0; sred1[tid] = p1;
            __syncthreads();
            for (int s = 128; s; s >>= 1) {
                if (tid < s) { sred0[tid] += sred0[tid + s]; sred1[tid] += sred1[tid + s]; }
                __syncthreads();
            }
            if (tid == 0) {
                float s0 = sred0[0], s1 = sred1[0];
                float m = fmaxf(s0, s1);
                float e0 = expf(s0 - m), e1 = expf(s1 - m);
                float inv = 1.f / (e0 + e1);
                s_a[0] = e0 * inv; s_a[1] = e1 * inv;
            }
            __syncthreads();
            float a0 = s_a[0], a1 = s_a[1];
#pragma unroll
            for (int i = 0; i < 4; ++i) {
                cA[i].x = a0 * hA[i].x + a1 * hA[i + 4].x;
                cA[i].y = a0 * hA[i].y + a1 * hA[i + 4].y;
                cA[i].z = a0 * hA[i].z + a1 * hA[i + 4].z;
                cA[i].w = a0 * hA[i].w + a1 * hA[i + 4].w;
                cB[i].x = a0 * hB[i].x + a1 * hB[i + 4].x;
                cB[i].y = a0 * hB[i].y + a1 * hB[i + 4].y;
                cB[i].z = a0 * hB[i].z + a1 * hB[i + 4].z;
                cB[i].w = a0 * hB[i].w + a1 * hB[i + 4].w;
            }
        }

        // ---------------- phase B ----------------
        // ids: [0,2048) GRU lane k | [2048,3072) u_r rows | [3072,3088) maxout finalize
        for (int id = gw; id < 3088; id += GWARPS) {
            if (id < D4) {
                int k = id;
                const uint4* Wr4 = reinterpret_cast<const uint4*>(g_wihc_h + (size_t)k * D2) + lane;
                const uint4* Wz4 = reinterpret_cast<const uint4*>(g_wihc_h + (size_t)(k + D4) * D2) + lane;
                const uint4* Wn4 = reinterpret_cast<const uint4*>(g_wihc_h + (size_t)(k + 2 * D4) * D2) + lane;
                float ar0 = 0.f, ar1 = 0.f, az0 = 0.f, az1 = 0.f, an0 = 0.f, an1 = 0.f;
#pragma unroll
                for (int i = 0; i < 4; ++i) {
                    uint4 rr_ = Wr4[i * 32];
                    uint4 rz_ = Wz4[i * 32];
                    uint4 rn_ = Wn4[i * 32];
                    FMA_H8(rr_, cA[i], cB[i], ar0, ar1);
                    FMA_H8(rz_, cA[i], cB[i], az0, az1);
                    FMA_H8(rn_, cA[i], cB[i], an0, an1);
                }
                float ar = wred(ar0 + ar1);
                float az = wred(az0 + az1);
                float an = wred(an0 + an1);
                if (lane == 0) {
                    const float* gi = g_GIw + (size_t)t * G3;
                    float rg = 1.f / (1.f + expf(-(gi[k]          + ar + g_gh[k])));
                    float zg = 1.f / (1.f + expf(-(gi[k + D4]     + az + g_gh[k + D4])));
                    float ng = tanhf(gi[k + 2 * D4] + an + rg * g_gh[k + 2 * D4]);
                    g_d[nxt][k] = (1.f - zg) * ng + zg * sh_h[k];
                }
            } else if (id < 3072) {
                int j = id - D4;
                const uint4* W4 = reinterpret_cast<const uint4*>(g_ur_h + (size_t)j * D2) + lane;
                float a0 = 0.f, a1 = 0.f;
#pragma unroll
                for (int i = 0; i < 4; ++i) {
                    uint4 raw = W4[i * 32];
                    FMA_H8(raw, cA[i], cB[i], a0, a1);
                }
                float dot = wred(a0 + a1);
                if (lane == 0)
                    g_rpart[cur][j] = g_RW[(size_t)t * D2 + j] + dot;
            } else {
                if (t > 0) {
                    int j = (id - 3072) * 32 + lane;
                    float f0 = g_rpart[nxt][j]      + g_vt[j];
                    float f1 = g_rpart[nxt][j + HH] + g_vt[j + HH];
                    g_rt[(size_t)(t - 1) * HH + j] = fmaxf(f0, f1);
                }
            }
        }
        ++gen; gsync(gen);
    }

    // ---------------- epilogue: finalize r_t for t=63 (h_new in g_d[0]) ----
    {
        const float4* src = reinterpret_cast<const float4*>(g_d[0]);
        float4* dst = reinterpret_cast<float4*>(sh_h);
        dst[tid] = src[tid];
        dst[tid + 256] = src[tid + 256];
        __syncthreads();
#pragma unroll
        for (int i = 0; i < 8; ++i) {
            hA[i] = *reinterpret_cast<const float4*>(sh_h + i * 256 + lane * 8);
            hB[i] = *reinterpret_cast<const float4*>(sh_h + i * 256 + lane * 8 + 4);
        }
        for (int id = gw; id < 1024; id += GWARPS) {
            const uint4* W4 = reinterpret_cast<const uint4*>(g_vr_h + (size_t)id * D4) + lane;
            float a0 = 0.f, a1 = 0.f;
#pragma unroll
            for (int i = 0; i < 8; ++i) {
                uint4 raw = W4[i * 32];
                FMA_H8(raw, hA[i], hB[i], a0, a1);
            }
            float dot = wred(a0 + a1);
            if (lane == 0) g_vt[id] = dot;
        }
        ++gen; gsync(gen);
        if (gw < 16) {                 // t=63 wrote g_rpart[1]
            int j = gw * 32 + lane;
            float f0 = g_rpart[1][j]      + g_vt[j];
            float f1 = g_rpart[1][j + HH] + g_vt[j + HH];
            g_rt[(size_t)63 * HH + j] = fmaxf(f0, f1);
        }
    }
}

// ---------------- logits GEMM: (64 x 512) @ wo^T (512 x 32000), FFMA2 ------
__global__ void __launch_bounds__(256) k_logits(const float* __restrict__ wo) {
    __shared__ __align__(16) float At2[32][144];  // At2[k][2m] = At2[k][2m+1] = A[m][k]
    __shared__ __align__(16) float Bt[32][136];   // Bt[k][n]
    const int tid = threadIdx.x;
    const int v0 = blockIdx.x * 128;              // 250 blocks
    const int tm = tid & 15, tn = tid >> 4;
    unsigned long long acc[4][4];
#pragma unroll
    for (int i = 0; i < 4; ++i)
#pragma unroll
        for (int j = 0; j < 4; ++j) acc[i][j] = 0ull;

    for (int k0 = 0; k0 < HH; k0 += 32) {
        __syncthreads();
#pragma unroll
        for (int it = 0; it < 2; ++it) {
            int i = tid + it * 256;
            int m = i >> 3, k4 = (i & 7) * 4;
            float4 v = *reinterpret_cast<const float4*>(g_rt + (size_t)m * HH + k0 + k4);
            At2[k4 + 0][2 * m] = v.x; At2[k4 + 0][2 * m + 1] = v.x;
            At2[k4 + 1][2 * m] = v.y; At2[k4 + 1][2 * m + 1] = v.y;
            At2[k4 + 2][2 * m] = v.z; At2[k4 + 2][2 * m + 1] = v.z;
            At2[k4 + 3][2 * m] = v.w; At2[k4 + 3][2 * m + 1] = v.w;
        }
#pragma unroll
        for (int it = 0; it < 4; ++it) {
            int i = tid + it * 256;
            int n = i >> 3, k4 = (i & 7) * 4;
            float4 v = *reinterpret_cast<const float4*>(wo + (size_t)(v0 + n) * HH + k0 + k4);
            Bt[k4 + 0][n] = v.x; Bt[k4 + 1][n] = v.y;
            Bt[k4 + 2][n] = v.z; Bt[k4 + 3][n] = v.w;
        }
        __syncthreads();
#pragma unroll
        for (int k = 0; k < 32; ++k) {
            ulonglong2 aA = *reinterpret_cast<const ulonglong2*>(&At2[k][tm * 8]);
            ulonglong2 aB = *reinterpret_cast<const ulonglong2*>(&At2[k][tm * 8 + 4]);
            ulonglong2 b0 = *reinterpret_cast<const ulonglong2*>(&Bt[k][tn * 8]);
            ulonglong2 b1 = *reinterpret_cast<const ulonglong2*>(&Bt[k][tn * 8 + 4]);
            FMA2(acc[0][0], aA.x, b0.x); FMA2(acc[0][1], aA.x, b0.y);
            FMA2(acc[0][2], aA.x, b1.x); FMA2(acc[0][3], aA.x, b1.y);
            FMA2(acc[1][0], aA.y, b0.x); FMA2(acc[1][1], aA.y, b0.y);
            FMA2(acc[1][2], aA.y, b1.x); FMA2(acc[1][3], aA.y, b1.y);
            FMA2(acc[2][0], aB.x, b0.x); FMA2(acc[2][1], aB.x, b0.y);
            FMA2(acc[2][2], aB.x, b1.x); FMA2(acc[2][3], aB.x, b1.y);
            FMA2(acc[3][0], aB.y, b0.x); FMA2(acc[3][1], aB.y, b0.y);
            FMA2(acc[3][2], aB.y, b1.x); FMA2(acc[3][3], aB.y, b1.y);
        }
    }
#pragma unroll
    for (int i = 0; i < 4; ++i) {
        float lo[4], hi[4];
#pragma unroll
        for (int j = 0; j < 4; ++j)
            asm("mov.b64 {%0, %1}, %2;" : "=f"(lo[j]), "=f"(hi[j]) : "l"(acc[i][j]));
        float* dst = g_logits + (size_t)(tm * 4 + i) * VV + v0 + tn * 8;
        *reinterpret_cast<float4*>(dst)     = make_float4(lo[0], hi[0], lo[1], hi[1]);
        *reinterpret_cast<float4*>(dst + 4) = make_float4(lo[2], hi[2], lo[3], hi[3]);
    }
}

// ---------------- row softmax over vocab -> d_out ----------------
__global__ void __launch_bounds__(512) k_softmax(float* __restrict__ out) {
    __shared__ float sh[512];
    const int row = blockIdx.x, tid = threadIdx.x;
    const float* lg = g_logits + (size_t)row * VV;
    float m = -INFINITY;
    for (int i = tid; i < VV; i += 512) m = fmaxf(m, lg[i]);
    sh[tid] = m; __syncthreads();
    for (int s = 256; s; s >>= 1) { if (tid < s) sh[tid] = fmaxf(sh[tid], sh[tid + s]); __syncthreads(); }
    m = sh[0]; __syncthreads();
    float sum = 0.f;
    for (int i = tid; i < VV; i += 512) sum += expf(lg[i] - m);
    sh[tid] = sum; __syncthreads();
    for (int s = 256; s; s >>= 1) { if (tid < s) sh[tid] += sh[tid + s]; __syncthreads(); }
    float inv = 1.f / sh[0];
    float* o = out + (size_t)row * VV;
    for (int i = tid; i < VV; i += 512) o[i] = expf(lg[i] - m) * inv;
}

// ---------------- launch ----------------
extern "C" void kernel_launch(void* const* d_in, const int* in_sizes, int n_in,
                              void* d_out, int out_size) {
    (void)in_sizes; (void)n_in; (void)out_size;
    const float* h_q    = (const float*)d_in[0];
    const float* h_p    = (const float*)d_in[1];
    const float* ans    = (const float*)d_in[2];
    const float* v_w    = (const float*)d_in[3];
    const float* w_d_w  = (const float*)d_in[4];
    const float* w_d_b  = (const float*)d_in[5];
    const float* w_a_w  = (const float*)d_in[6];
    const float* u_a_w  = (const float*)d_in[7];
    const float* w_r_w  = (const float*)d_in[8];
    const float* u_r_w  = (const float*)d_in[9];
    const float* v_r_w  = (const float*)d_in[10];
    const float* w_o_w  = (const float*)d_in[11];
    const float* gw_ih  = (const float*)d_in[12];
    const float* gw_hh  = (const float*)d_in[13];
    const float* gb_ih  = (const float*)d_in[14];
    const float* gb_hh  = (const float*)d_in[15];
    float* out = (float*)d_out;

    // fp16 weight conversion (one-time per launch, ~35us of DRAM traffic)
    const int n_conv4 = (G3 * D4 + D2 * D4 + D2 * D2 + D2 * D2) / 4;
    k_conv4<<<(n_conv4 + 255) / 256, 256>>>(gw_hh, v_r_w, u_r_w, w_a_w);
    k_conv_wihc<<<(G3 * (D2 / 4) + 255) / 256, 256>>>(gw_ih);

    k_colsum<<<64, 256>>>(h_q, h_p);
    k_finish_h<<<4, 256>>>();
    k_rows<<<384, 256>>>(u_a_w, w_d_w, w_d_b, h_q, h_p);
    k_gemm0<<<112, 256>>>(gw_ih, w_r_w, gb_ih, ans);
    k_persist<<<NB, NT>>>(v_w, gb_hh);
    k_logits<<<VV / 128, 256>>>(w_o_w);
    k_softmax<<<LL, 512>>>(out);
}

// round 14
// speedup vs baseline: 1.2388x; 1.0623x over previous
#include <cuda_runtime.h>
#include <cuda_fp16.h>
#include <math.h>

// ---------------- problem dims ----------------
#define D2 1024          // 2H
#define D4 2048          // 4H
#define G3 6144          // 3*D4
#define LL 64            // answer length
#define VV 32000         // vocab
#define HH 512           // H
#define NQ 32
#define NSUM 4128        // 32 + 4096

// ---------------- persistent kernel config ----------------
#define NB 148           // 1 CTA/SM resident (152-SM part idles 4 SMs; never deadlocks)
#define NT 256
#define NWARP 8
#define GWARPS (NB * NWARP)   // 1184

// ---------------- device scratch (static, no allocation) ----------------
__device__ __align__(16) float g_hpart[64 * D2];
__device__ __align__(16) float g_h[D2];
__device__ __align__(16) float g_uah[D2];
__device__ __align__(16) float g_d[2][D4];       // decoder state double buffer
__device__ __align__(16) float g_gh[G3];         // W_hh @ hprev + b_hh
__device__ __align__(16) float g_scon[2 * D2];   // score contributions v[j]*tanh(...)
__device__ __align__(16) float g_vt[D2];         // v_r @ hprev partials
__device__ __align__(16) float g_GIw[LL * G3];   // precomputed W_ih[:, :D2] @ w_t + b_ih
__device__ __align__(16) float g_RW[LL * D2];    // precomputed w_r @ w_t
__device__ __align__(16) float g_rpart[2][D2];   // RW[t] + u_r @ c   (parity-buffered)
__device__ __align__(16) float g_rt[LL * HH];    // maxout outputs (logits A operand)
__device__ __align__(16) float g_logits[LL * VV];
__device__ unsigned g_bar_cnt;                   // zero-init; returns to 0 each launch
__device__ unsigned g_bar_gen;                   // monotonic across graph replays

// fp16 copies of the loop-resident weight matrices (~46 MB total)
__device__ __align__(16) __half g_whh_h[G3 * D4];    // 25.2 MB
__device__ __align__(16) __half g_wihc_h[G3 * D2];   // 12.6 MB (c-half of W_ih, compact)
__device__ __align__(16) __half g_vr_h[D2 * D4];     //  4.2 MB
__device__ __align__(16) __half g_ur_h[D2 * D2];     //  2.1 MB
__device__ __align__(16) __half g_wa_h[D2 * D2];     //  2.1 MB

// ---------------- helpers ----------------
__device__ __forceinline__ float wred(float v) {
#pragma unroll
    for (int o = 16; o; o >>= 1) v += __shfl_xor_sync(0xffffffffu, v, o);
    return v;
}

// interleaved dual/triple reductions: shfl chains overlap (lat 26, issue 1/cyc)
__device__ __forceinline__ void wred2(float& a, float& b) {
#pragma unroll
    for (int o = 16; o; o >>= 1) {
        float ta = __shfl_xor_sync(0xffffffffu, a, o);
        float tb = __shfl_xor_sync(0xffffffffu, b, o);
        a += ta; b += tb;
    }
}
__device__ __forceinline__ void wred3(float& a, float& b, float& c) {
#pragma unroll
    for (int o = 16; o; o >>= 1) {
        float ta = __shfl_xor_sync(0xffffffffu, a, o);
        float tb = __shfl_xor_sync(0xffffffffu, b, o);
        float tc = __shfl_xor_sync(0xffffffffu, c, o);
        a += ta; b += tb; c += tc;
    }
}

template <int LEN>
__device__ __forceinline__ float warp_dot(const float* __restrict__ w,
                                          const float* __restrict__ v, int lane) {
    constexpr int NI = LEN / 128;
    float acc = 0.f;
#pragma unroll
    for (int i = 0; i < NI; ++i) {
        float4 a = *reinterpret_cast<const float4*>(w + i * 128 + lane * 4);
        float4 b = *reinterpret_cast<const float4*>(v + i * 128 + lane * 4);
        acc = fmaf(a.x, b.x, acc); acc = fmaf(a.y, b.y, acc);
        acc = fmaf(a.z, b.z, acc); acc = fmaf(a.w, b.w, acc);
    }
    return wred(acc);
}

// Replay-safe generation grid barrier (validated in two passing runs).
__device__ __forceinline__ void gsync(unsigned gen) {
    __syncthreads();
    if (threadIdx.x == 0) {
        __threadfence();
        unsigned prev = atomicAdd(&g_bar_cnt, 1u);
        if (prev == NB - 1u) {
            g_bar_cnt = 0u;
            __threadfence();
            *(volatile unsigned*)&g_bar_gen = gen;
        } else {
            while ((int)(*(volatile unsigned*)&g_bar_gen - gen) < 0) __nanosleep(64);
            __threadfence();
        }
    }
    __syncthreads();
}

// packed fp32x2 FMA (Blackwell FFMA2 — only reachable via PTX)
#define FMA2(c, a, b) \
    asm("fma.rn.f32x2 %0, %1, %2, %0;" : "+l"(c) : "l"(a), "l"(b))

// fma of 8 fp16 weights (as uint4) against two float4 halves of the vector
#define FMA_H8(raw, va, vb, acc0, acc1) do {                                   \
    const __half2* _hp = reinterpret_cast<const __half2*>(&(raw));             \
    float2 _w0 = __half22float2(_hp[0]); float2 _w1 = __half22float2(_hp[1]);  \
    float2 _w2 = __half22float2(_hp[2]); float2 _w3 = __half22float2(_hp[3]);  \
    acc0 = fmaf(_w0.x, (va).x, acc0); acc0 = fmaf(_w0.y, (va).y, acc0);        \
    acc0 = fmaf(_w1.x, (va).z, acc0); acc0 = fmaf(_w1.y, (va).w, acc0);        \
    acc1 = fmaf(_w2.x, (vb).x, acc1); acc1 = fmaf(_w2.y, (vb).y, acc1);        \
    acc1 = fmaf(_w3.x, (vb).z, acc1); acc1 = fmaf(_w3.y, (vb).w, acc1);        \
} while (0)

// ---------------- weight conversion kernels ----------------
__global__ void k_conv4(const float* __restrict__ whh, const float* __restrict__ vr,
                        const float* __restrict__ ur, const float* __restrict__ wa) {
    const int n_whh = G3 * D4 / 4, n_vr = D2 * D4 / 4, n_ur = D2 * D2 / 4, n_wa = D2 * D2 / 4;
    int i = blockIdx.x * blockDim.x + threadIdx.x;
    const float* src; __half* dst; int off;
    if (i < n_whh)                            { src = whh; dst = g_whh_h; off = i; }
    else if ((i -= n_whh) < n_vr)             { src = vr;  dst = g_vr_h;  off = i; }
    else if ((i -= n_vr) < n_ur)              { src = ur;  dst = g_ur_h;  off = i; }
    else if ((i -= n_ur) < n_wa)              { src = wa;  dst = g_wa_h;  off = i; }
    else return;
    float4 v = reinterpret_cast<const float4*>(src)[off];
    __half2 h0 = __floats2half2_rn(v.x, v.y);
    __half2 h1 = __floats2half2_rn(v.z, v.w);
    reinterpret_cast<__half2*>(dst)[2 * off]     = h0;
    reinterpret_cast<__half2*>(dst)[2 * off + 1] = h1;
}

__global__ void k_conv_wihc(const float* __restrict__ w_ih) {
    int i = blockIdx.x * blockDim.x + threadIdx.x;   // over G3 * D2/4
    if (i < G3 * (D2 / 4)) {
        int r = i / (D2 / 4), c4 = (i % (D2 / 4)) * 4;
        float4 v = *reinterpret_cast<const float4*>(w_ih + (size_t)r * D4 + D2 + c4);
        __half2 h0 = __floats2half2_rn(v.x, v.y);
        __half2 h1 = __floats2half2_rn(v.z, v.w);
        __half2* dst = reinterpret_cast<__half2*>(g_wihc_h + (size_t)r * D2 + c4);
        dst[0] = h0; dst[1] = h1;
    }
}

// ---------------- setup kernels ----------------
__global__ void k_colsum(const float* __restrict__ h_q, const float* __restrict__ h_p) {
    int b = blockIdx.x;
    int r0 = b * 65, r1 = min(r0 + 65, NSUM);
    int c = threadIdx.x;
    float acc[4] = {0.f, 0.f, 0.f, 0.f};
    for (int r = r0; r < r1; ++r) {
        const float* src = (r < NQ) ? (h_q + (size_t)r * D2) : (h_p + (size_t)(r - NQ) * D2);
#pragma unroll
        for (int i = 0; i < 4; ++i) acc[i] += src[c + i * 256];
    }
#pragma unroll
    for (int i = 0; i < 4; ++i) g_hpart[b * D2 + c + i * 256] = acc[i];
}

__global__ void k_finish_h() {
    int c = blockIdx.x * 256 + threadIdx.x;
    float s = 0.f;
#pragma unroll
    for (int b = 0; b < 64; ++b) s += g_hpart[b * D2 + c];   // full unroll: MLP
    g_h[c] = s;
}

__global__ void k_rows(const float* __restrict__ u_a, const float* __restrict__ w_d,
                       const float* __restrict__ w_d_b,
                       const float* __restrict__ h_q, const float* __restrict__ h_p) {
    int warp = threadIdx.x >> 5, lane = threadIdx.x & 31;
    int row = blockIdx.x * 8 + warp;
    if (row < D2) {
        float dot = warp_dot<D2>(u_a + (size_t)row * D2, g_h, lane);
        if (lane == 0) g_uah[row] = dot;
    } else if (row < 2 * D2) {
        int j = row - D2;
        float dot = warp_dot<D2>(w_d + (size_t)j * D2, h_q, lane);
        if (lane == 0) g_d[0][j] = tanhf(dot + w_d_b[j]);
    } else {
        int j = row - 2 * D2;
        float dot = warp_dot<D2>(w_d + (size_t)j * D2, h_p, lane);
        if (lane == 0) g_d[0][D2 + j] = tanhf(dot + w_d_b[j]);
    }
}

// GIw[t][r] = W_ih[r, :D2] @ ans[t] + b_ih[r]  (rows 0..6143)
// RW [t][j] = w_r[j] @ ans[t]                  (rows 6144..7167)
// Register double-buffering: next tile's global loads overlap current compute.
__global__ void __launch_bounds__(256) k_gemm0(
    const float* __restrict__ w_ih, const float* __restrict__ w_r,
    const float* __restrict__ b_ih, const float* __restrict__ ans) {
    __shared__ __align__(16) float Wt[32][68];
    __shared__ __align__(16) float At[32][68];
    int rbase = blockIdx.x * 64;
    int tid = threadIdx.x;
    int rr = tid & 15, tt = tid >> 4;
    float acc[4][4];
#pragma unroll
    for (int i = 0; i < 4; ++i)
#pragma unroll
        for (int j = 0; j < 4; ++j) acc[i][j] = 0.f;

    float4 wv[2], av[2];
    // prefetch k0 = 0
#pragma unroll
    for (int it = 0; it < 2; ++it) {
        int i = tid + it * 256;
        int r = i >> 3, k4 = (i & 7) * 4;
        int row = rbase + r;
        const float* src = (row < G3) ? (w_ih + (size_t)row * D4)
                                      : (w_r + (size_t)(row - G3) * D2);
        wv[it] = *reinterpret_cast<const float4*>(src + k4);
        av[it] = *reinterpret_cast<const float4*>(ans + (size_t)r * D2 + k4);
    }

    for (int k0 = 0; k0 < D2; k0 += 32) {
        __syncthreads();
#pragma unroll
        for (int it = 0; it < 2; ++it) {
            int i = tid + it * 256;
            int r = i >> 3, k4 = (i & 7) * 4;
            Wt[k4 + 0][r] = wv[it].x; Wt[k4 + 1][r] = wv[it].y;
            Wt[k4 + 2][r] = wv[it].z; Wt[k4 + 3][r] = wv[it].w;
            At[k4 + 0][r] = av[it].x; At[k4 + 1][r] = av[it].y;
            At[k4 + 2][r] = av[it].z; At[k4 + 3][r] = av[it].w;
        }
        __syncthreads();
        int kn = k0 + 32;
        if (kn < D2) {
#pragma unroll
            for (int it = 0; it < 2; ++it) {
                int i = tid + it * 256;
                int r = i >> 3, k4 = (i & 7) * 4;
                int row = rbase + r;
                const float* src = (row < G3) ? (w_ih + (size_t)row * D4)
                                              : (w_r + (size_t)(row - G3) * D2);
                wv[it] = *reinterpret_cast<const float4*>(src + kn + k4);
                av[it] = *reinterpret_cast<const float4*>(ans + (size_t)r * D2 + kn + k4);
            }
        }
#pragma unroll
        for (int k = 0; k < 32; ++k) {
            float4 wv_ = *reinterpret_cast<const float4*>(&Wt[k][rr * 4]);
            float4 av_ = *reinterpret_cast<const float4*>(&At[k][tt * 4]);
            float wa[4] = {wv_.x, wv_.y, wv_.z, wv_.w};
            float aa[4] = {av_.x, av_.y, av_.z, av_.w};
#pragma unroll
            for (int i = 0; i < 4; ++i)
#pragma unroll
                for (int j = 0; j < 4; ++j)
                    acc[i][j] = fmaf(wa[i], aa[j], acc[i][j]);
        }
    }
#pragma unroll
    for (int i = 0; i < 4; ++i) {
        int row = rbase + rr * 4 + i;
        float b = (row < G3) ? b_ih[row] : 0.f;
#pragma unroll
        for (int j = 0; j < 4; ++j) {
            int t = tt * 4 + j;
            float v = acc[i][j] + b;
            if (row < G3) g_GIw[(size_t)t * G3 + row] = v;
            else          g_RW[(size_t)t * D2 + (row - G3)] = v;
        }
    }
}

// ---------------- persistent recurrence kernel (fp16, latency-optimized) ---
__global__ void __launch_bounds__(NT, 1) k_persist(
    const float* __restrict__ v_w, const float* __restrict__ b_hh) {
    const int tid = threadIdx.x;
    const int wid = tid >> 5, lane = tid & 31;
    const int gw = blockIdx.x * NWARP + wid;
    __shared__ __align__(16) float sh_h[D4];   // hprev broadcast (8KB)
    __shared__ float sred0[NT];
    __shared__ float sred1[NT];
    __shared__ float s_a[2];
    __shared__ unsigned s_gen;

    if (tid == 0) s_gen = *(volatile unsigned*)&g_bar_gen;
    __syncthreads();
    unsigned gen = s_gen;

    // lane slicing: chunk i covers vector elements [i*256 + lane*8, +8)
    float4 hA[8], hB[8];   // hprev slice (D4)
    float4 cA[4], cB[4];   // context slice (D2)

    for (int t = 0; t < LL; ++t) {
        const int cur = t & 1, nxt = cur ^ 1;
        {
            const float4* src = reinterpret_cast<const float4*>(g_d[cur]);
            float4* dst = reinterpret_cast<float4*>(sh_h);
            dst[tid] = src[tid];
            dst[tid + 256] = src[tid + 256];
        }
        __syncthreads();
#pragma unroll
        for (int i = 0; i < 8; ++i) {
            hA[i] = *reinterpret_cast<const float4*>(sh_h + i * 256 + lane * 8);
            hB[i] = *reinterpret_cast<const float4*>(sh_h + i * 256 + lane * 8 + 4);
        }

        // ---------------- phase A ----------------
        // ids: [0,3072) W_hh row pairs (8KB, 16 loads in flight)
        //      [3072,3584) v_r row pairs (8KB) | [3584,4608) attention rows (2KB)
        for (int id = gw; id < 4608; id += GWARPS) {
            if (id < 3072) {
                int r = id * 2;
                const uint4* W0 = reinterpret_cast<const uint4*>(g_whh_h + (size_t)r * D4) + lane;
                const uint4* W1 = W0 + (D4 / 8);
                float a0 = 0.f, a1 = 0.f, b0 = 0.f, b1 = 0.f;
#pragma unroll
                for (int i = 0; i < 8; ++i) {
                    uint4 r0 = W0[i * 32];
                    uint4 r1 = W1[i * 32];
                    FMA_H8(r0, hA[i], hB[i], a0, a1);
                    FMA_H8(r1, hA[i], hB[i], b0, b1);
                }
                float da = a0 + a1, db = b0 + b1;
                wred2(da, db);
                if (lane == 0) {
                    g_gh[r]     = da + b_hh[r];
                    g_gh[r + 1] = db + b_hh[r + 1];
                }
            } else if (id < 3584) {
                int j = (id - 3072) * 2;
                const uint4* W0 = reinterpret_cast<const uint4*>(g_vr_h + (size_t)j * D4) + lane;
                const uint4* W1 = W0 + (D4 / 8);
                float a0 = 0.f, a1 = 0.f, b0 = 0.f, b1 = 0.f;
#pragma unroll
                for (int i = 0; i < 8; ++i) {
                    uint4 r0 = W0[i * 32];
                    uint4 r1 = W1[i * 32];
                    FMA_H8(r0, hA[i], hB[i], a0, a1);
                    FMA_H8(r1, hA[i], hB[i], b0, b1);
                }
                float da = a0 + a1, db = b0 + b1;
                wred2(da, db);
                if (lane == 0) {
                    g_vt[j]     = da;
                    g_vt[j + 1] = db;
                }
            } else {
                int j = id - 3584;
                const uint4* W4 = reinterpret_cast<const uint4*>(g_wa_h + (size_t)j * D2) + lane;
                float s0a = 0.f, s0b = 0.f, s1a = 0.f, s1b = 0.f;
#pragma unroll
                for (int i = 0; i < 4; ++i) {
                    uint4 raw = W4[i * 32];
                    const __half2* hp = reinterpret_cast<const __half2*>(&raw);
                    float2 w0 = __half22float2(hp[0]); float2 w1 = __half22float2(hp[1]);
                    float2 w2 = __half22float2(hp[2]); float2 w3 = __half22float2(hp[3]);
                    s0a = fmaf(w0.x, hA[i].x, s0a); s0a = fmaf(w0.y, hA[i].y, s0a);
                    s0a = fmaf(w1.x, hA[i].z, s0a); s0a = fmaf(w1.y, hA[i].w, s0a);
                    s0b = fmaf(w2.x, hB[i].x, s0b); s0b = fmaf(w2.y, hB[i].y, s0b);
                    s0b = fmaf(w3.x, hB[i].z, s0b); s0b = fmaf(w3.y, hB[i].w, s0b);
                    s1a = fmaf(w0.x, hA[i + 4].x, s1a); s1a = fmaf(w0.y, hA[i + 4].y, s1a);
                    s1a = fmaf(w1.x, hA[i + 4].z, s1a); s1a = fmaf(w1.y, hA[i + 4].w, s1a);
                    s1b = fmaf(w2.x, hB[i + 4].x, s1b); s1b = fmaf(w2.y, hB[i + 4].y, s1b);
                    s1b = fmaf(w3.x, hB[i + 4].z, s1b); s1b = fmaf(w3.y, hB[i + 4].w, s1b);
                }
                float a0 = s0a + s0b, a1 = s1a + s1b;
                wred2(a0, a1);
                if (lane == 0) {
                    float vj = v_w[j], uj = g_uah[j];
                    g_scon[j]      = vj * tanhf(a0 + uj);
                    g_scon[D2 + j] = vj * tanhf(a1 + uj);
                }
            }
        }
        ++gen; gsync(gen);

        // ---------------- phase B preamble: scores -> a -> c (registers) ----
        {
            float p0 = 0.f, p1 = 0.f;
#pragma unroll
            for (int kk = 0; kk < 4; ++kk) {
                p0 += g_scon[tid + kk * 256];
                p1 += g_scon[D2 + tid + kk * 256];
            }
            sred0[tid] = p0; sred1[tid] = p1;
            __syncthreads();
            for (int s = 128; s; s >>= 1) {
                if (tid < s) { sred0[tid] += sred0[tid + s]; sred1[tid] += sred1[tid + s]; }
                __syncthreads();
            }
            if (tid == 0) {
                float s0 = sred0[0], s1 = sred1[0];
                float m = fmaxf(s0, s1);
                float e0 = expf(s0 - m), e1 = expf(s1 - m);
                float inv = 1.f / (e0 + e1);
                s_a[0] = e0 * inv; s_a[1] = e1 * inv;
            }
            __syncthreads();
            float a0 = s_a[0], a1 = s_a[1];
#pragma unroll
            for (int i = 0; i < 4; ++i) {
                cA[i].x = a0 * hA[i].x + a1 * hA[i + 4].x;
                cA[i].y = a0 * hA[i].y + a1 * hA[i + 4].y;
                cA[i].z = a0 * hA[i].z + a1 * hA[i + 4].z;
                cA[i].w = a0 * hA[i].w + a1 * hA[i + 4].w;
                cB[i].x = a0 * hB[i].x + a1 * hB[i + 4].x;
                cB[i].y = a0 * hB[i].y + a1 * hB[i + 4].y;
                cB[i].z = a0 * hB[i].z + a1 * hB[i + 4].z;
                cB[i].w = a0 * hB[i].w + a1 * hB[i + 4].w;
            }
        }

        // ---------------- phase B ----------------
        // ids: [0,2048) GRU lane k (12 loads, wred3) | [2048,3072) u_r rows
        //      [3072,3088) maxout finalize
        for (int id = gw; id < 3088; id += GWARPS) {
            if (id < D4) {
                int k = id;
                const uint4* Wr4 = reinterpret_cast<const uint4*>(g_wihc_h + (size_t)k * D2) + lane;
                const uint4* Wz4 = reinterpret_cast<const uint4*>(g_wihc_h + (size_t)(k + D4) * D2) + lane;
                const uint4* Wn4 = reinterpret_cast<const uint4*>(g_wihc_h + (size_t)(k + 2 * D4) * D2) + lane;
                float ar0 = 0.f, ar1 = 0.f, az0 = 0.f, az1 = 0.f, an0 = 0.f, an1 = 0.f;
#pragma unroll
                for (int i = 0; i < 4; ++i) {
                    uint4 rr_ = Wr4[i * 32];
                    uint4 rz_ = Wz4[i * 32];
                    uint4 rn_ = Wn4[i * 32];
                    FMA_H8(rr_, cA[i], cB[i], ar0, ar1);
                    FMA_H8(rz_, cA[i], cB[i], az0, az1);
                    FMA_H8(rn_, cA[i], cB[i], an0, an1);
                }
                float ar = ar0 + ar1, az = az0 + az1, an = an0 + an1;
                wred3(ar, az, an);
                if (lane == 0) {
                    const float* gi = g_GIw + (size_t)t * G3;
                    float rg = 1.f / (1.f + expf(-(gi[k]          + ar + g_gh[k])));
                    float zg = 1.f / (1.f + expf(-(gi[k + D4]     + az + g_gh[k + D4])));
                    float ng = tanhf(gi[k + 2 * D4] + an + rg * g_gh[k + 2 * D4]);
                    g_d[nxt][k] = (1.f - zg) * ng + zg * sh_h[k];
                }
            } else if (id < 3072) {
                int j = id - D4;
                const uint4* W4 = reinterpret_cast<const uint4*>(g_ur_h + (size_t)j * D2) + lane;
                float a0 = 0.f, a1 = 0.f;
#pragma unroll
                for (int i = 0; i < 4; ++i) {
                    uint4 raw = W4[i * 32];
                    FMA_H8(raw, cA[i], cB[i], a0, a1);
                }
                float dot = wred(a0 + a1);
                if (lane == 0)
                    g_rpart[cur][j] = g_RW[(size_t)t * D2 + j] + dot;
            } else {
                if (t > 0) {
                    int j = (id - 3072) * 32 + lane;
                    float f0 = g_rpart[nxt][j]      + g_vt[j];
                    float f1 = g_rpart[nxt][j + HH] + g_vt[j + HH];
                    g_rt[(size_t)(t - 1) * HH + j] = fmaxf(f0, f1);
                }
            }
        }
        ++gen; gsync(gen);
    }

    // ---------------- epilogue: finalize r_t for t=63 (h_new in g_d[0]) ----
    {
        const float4* src = reinterpret_cast<const float4*>(g_d[0]);
        float4* dst = reinterpret_cast<float4*>(sh_h);
        dst[tid] = src[tid];
        dst[tid + 256] = src[tid + 256];
        __syncthreads();
#pragma unroll
        for (int i = 0; i < 8; ++i) {
            hA[i] = *reinterpret_cast<const float4*>(sh_h + i * 256 + lane * 8);
            hB[i] = *reinterpret_cast<const float4*>(sh_h + i * 256 + lane * 8 + 4);
        }
        for (int id = gw; id < 512; id += GWARPS) {
            int j = id * 2;
            const uint4* W0 = reinterpret_cast<const uint4*>(g_vr_h + (size_t)j * D4) + lane;
            const uint4* W1 = W0 + (D4 / 8);
            float a0 = 0.f, a1 = 0.f, b0 = 0.f, b1 = 0.f;
#pragma unroll
            for (int i = 0; i < 8; ++i) {
                uint4 r0 = W0[i * 32];
                uint4 r1 = W1[i * 32];
                FMA_H8(r0, hA[i], hB[i], a0, a1);
                FMA_H8(r1, hA[i], hB[i], b0, b1);
            }
            float da = a0 + a1, db = b0 + b1;
            wred2(da, db);
            if (lane == 0) { g_vt[j] = da; g_vt[j + 1] = db; }
        }
        ++gen; gsync(gen);
        if (gw < 16) {                 // t=63 wrote g_rpart[1]
            int j = gw * 32 + lane;
            float f0 = g_rpart[1][j]      + g_vt[j];
            float f1 = g_rpart[1][j + HH] + g_vt[j + HH];
            g_rt[(size_t)63 * HH + j] = fmaxf(f0, f1);
        }
    }
}

// ---------------- logits GEMM: (64 x 512) @ wo^T (512 x 32000), FFMA2 ------
__global__ void __launch_bounds__(256) k_logits(const float* __restrict__ wo) {
    __shared__ __align__(16) float At2[32][144];  // At2[k][2m] = At2[k][2m+1] = A[m][k]
    __shared__ __align__(16) float Bt[32][136];   // Bt[k][n]
    const int tid = threadIdx.x;
    const int v0 = blockIdx.x * 128;              // 250 blocks
    const int tm = tid & 15, tn = tid >> 4;
    unsigned long long acc[4][4];
#pragma unroll
    for (int i = 0; i < 4; ++i)
#pragma unroll
        for (int j = 0; j < 4; ++j) acc[i][j] = 0ull;

    for (int k0 = 0; k0 < HH; k0 += 32) {
        __syncthreads();
#pragma unroll
        for (int it = 0; it < 2; ++it) {
            int i = tid + it * 256;
            int m = i >> 3, k4 = (i & 7) * 4;
            float4 v = *reinterpret_cast<const float4*>(g_rt + (size_t)m * HH + k0 + k4);
            At2[k4 + 0][2 * m] = v.x; At2[k4 + 0][2 * m + 1] = v.x;
            At2[k4 + 1][2 * m] = v.y; At2[k4 + 1][2 * m + 1] = v.y;
            At2[k4 + 2][2 * m] = v.z; At2[k4 + 2][2 * m + 1] = v.z;
            At2[k4 + 3][2 * m] = v.w; At2[k4 + 3][2 * m + 1] = v.w;
        }
#pragma unroll
        for (int it = 0; it < 4; ++it) {
            int i = tid + it * 256;
            int n = i >> 3, k4 = (i & 7) * 4;
            float4 v = *reinterpret_cast<const float4*>(wo + (size_t)(v0 + n) * HH + k0 + k4);
            Bt[k4 + 0][n] = v.x; Bt[k4 + 1][n] = v.y;
            Bt[k4 + 2][n] = v.z; Bt[k4 + 3][n] = v.w;
        }
        __syncthreads();
#pragma unroll
        for (int k = 0; k < 32; ++k) {
            ulonglong2 aA = *reinterpret_cast<const ulonglong2*>(&At2[k][tm * 8]);
            ulonglong2 aB = *reinterpret_cast<const ulonglong2*>(&At2[k][tm * 8 + 4]);
            ulonglong2 b0 = *reinterpret_cast<const ulonglong2*>(&Bt[k][tn * 8]);
            ulonglong2 b1 = *reinterpret_cast<const ulonglong2*>(&Bt[k][tn * 8 + 4]);
            FMA2(acc[0][0], aA.x, b0.x); FMA2(acc[0][1], aA.x, b0.y);
            FMA2(acc[0][2], aA.x, b1.x); FMA2(acc[0][3], aA.x, b1.y);
            FMA2(acc[1][0], aA.y, b0.x); FMA2(acc[1][1], aA.y, b0.y);
            FMA2(acc[1][2], aA.y, b1.x); FMA2(acc[1][3], aA.y, b1.y);
            FMA2(acc[2][0], aB.x, b0.x); FMA2(acc[2][1], aB.x, b0.y);
            FMA2(acc[2][2], aB.x, b1.x); FMA2(acc[2][3], aB.x, b1.y);
            FMA2(acc[3][0], aB.y, b0.x); FMA2(acc[3][1], aB.y, b0.y);
            FMA2(acc[3][2], aB.y, b1.x); FMA2(acc[3][3], aB.y, b1.y);
        }
    }
#pragma unroll
    for (int i = 0; i < 4; ++i) {
        float lo[4], hi[4];
#pragma unroll
        for (int j = 0; j < 4; ++j)
            asm("mov.b64 {%0, %1}, %2;" : "=f"(lo[j]), "=f"(hi[j]) : "l"(acc[i][j]));
        float* dst = g_logits + (size_t)(tm * 4 + i) * VV + v0 + tn * 8;
        *reinterpret_cast<float4*>(dst)     = make_float4(lo[0], hi[0], lo[1], hi[1]);
        *reinterpret_cast<float4*>(dst + 4) = make_float4(lo[2], hi[2], lo[3], hi[3]);
    }
}

// ---------------- row softmax over vocab -> d_out ----------------
__global__ void __launch_bounds__(512) k_softmax(float* __restrict__ out) {
    __shared__ float sh[512];
    const int row = blockIdx.x, tid = threadIdx.x;
    const float* lg = g_logits + (size_t)row * VV;
    float m = -INFINITY;
    for (int i = tid; i < VV; i += 512) m = fmaxf(m, lg[i]);
    sh[tid] = m; __syncthreads();
    for (int s = 256; s; s >>= 1) { if (tid < s) sh[tid] = fmaxf(sh[tid], sh[tid + s]); __syncthreads(); }
    m = sh[0]; __syncthreads();
    float sum = 0.f;
    for (int i = tid; i < VV; i += 512) sum += expf(lg[i] - m);
    sh[tid] = sum; __syncthreads();
    for (int s = 256; s; s >>= 1) { if (tid < s) sh[tid] += sh[tid + s]; __syncthreads(); }
    float inv = 1.f / sh[0];
    float* o = out + (size_t)row * VV;
    for (int i = tid; i < VV; i += 512) o[i] = expf(lg[i] - m) * inv;
}

// ---------------- launch ----------------
extern "C" void kernel_launch(void* const* d_in, const int* in_sizes, int n_in,
                              void* d_out, int out_size) {
    (void)in_sizes; (void)n_in; (void)out_size;
    const float* h_q    = (const float*)d_in[0];
    const float* h_p    = (const float*)d_in[1];
    const float* ans    = (const float*)d_in[2];
    const float* v_w    = (const float*)d_in[3];
    const float* w_d_w  = (const float*)d_in[4];
    const float* w_d_b  = (const float*)d_in[5];
    const float* w_a_w  = (const float*)d_in[6];
    const float* u_a_w  = (const float*)d_in[7];
    const float* w_r_w  = (const float*)d_in[8];
    const float* u_r_w  = (const float*)d_in[9];
    const float* v_r_w  = (const float*)d_in[10];
    const float* w_o_w  = (const float*)d_in[11];
    const float* gw_ih  = (const float*)d_in[12];
    const float* gw_hh  = (const float*)d_in[13];
    const float* gb_ih  = (const float*)d_in[14];
    const float* gb_hh  = (const float*)d_in[15];
    float* out = (float*)d_out;

    // fp16 weight conversion (one-time per launch, ~35us of DRAM traffic)
    const int n_conv4 = (G3 * D4 + D2 * D4 + D2 * D2 + D2 * D2) / 4;
    k_conv4<<<(n_conv4 + 255) / 256, 256>>>(gw_hh, v_r_w, u_r_w, w_a_w);
    k_conv_wihc<<<(G3 * (D2 / 4) + 255) / 256, 256>>>(gw_ih);

    k_colsum<<<64, 256>>>(h_q, h_p);
    k_finish_h<<<4, 256>>>();
    k_rows<<<384, 256>>>(u_a_w, w_d_w, w_d_b, h_q, h_p);
    k_gemm0<<<112, 256>>>(gw_ih, w_r_w, gb_ih, ans);
    k_persist<<<NB, NT>>>(v_w, gb_hh);
    k_logits<<<VV / 128, 256>>>(w_o_w);
    k_softmax<<<LL, 512>>>(out);
}

// round 15
// speedup vs baseline: 1.4245x; 1.1500x over previous
#include <cuda_runtime.h>
#include <cuda_fp16.h>
#include <math.h>

// ---------------- problem dims ----------------
#define D2 1024          // 2H
#define D4 2048          // 4H
#define G3 6144          // 3*D4
#define LL 64            // answer length
#define VV 32000         // vocab
#define HH 512           // H
#define NQ 32
#define NSUM 4128        // 32 + 4096

// ---------------- persistent kernel config ----------------
#define NB 296           // 2 CTAs/SM on 148 SMs (guaranteed by launch_bounds(256,2))
#define NT 256
#define NWARP 8
#define GWARPS (NB * NWARP)   // 2368

// ---------------- device scratch (static, no allocation) ----------------
__device__ __align__(16) float g_hpart[64 * D2];
__device__ __align__(16) float g_h[D2];
__device__ __align__(16) float g_uah[D2];
__device__ __align__(16) float g_d[2][D4];       // decoder state double buffer
__device__ __align__(16) float g_gh[G3];         // W_hh @ hprev + b_hh
__device__ __align__(16) float g_scon[2 * D2];   // score contributions v[j]*tanh(...)
__device__ __align__(16) float g_vt[D2];         // v_r @ hprev partials
__device__ __align__(16) float g_GIw[LL * G3];   // precomputed W_ih[:, :D2] @ w_t + b_ih
__device__ __align__(16) float g_RW[LL * D2];    // precomputed w_r @ w_t
__device__ __align__(16) float g_rpart[2][D2];   // RW[t] + u_r @ c   (parity-buffered)
__device__ __align__(16) float g_rt[LL * HH];    // maxout outputs (logits A operand)
__device__ __align__(16) float g_logits[LL * VV];
__device__ unsigned g_bar_cnt;                   // zero-init; returns to 0 each launch
__device__ unsigned g_bar_gen;                   // monotonic across graph replays

// fp16 copies of the loop-resident weight matrices (~46 MB total), PERMUTED:
// within each row, uint4 slot s = i*32+l packs halves for elements
// {i*256 + l*4 .. +3} then {i*256 + 128 + l*4 .. +3}  -> conflict-free LDS
__device__ __align__(16) __half g_whh_h[G3 * D4];    // 25.2 MB (rows of 2048)
__device__ __align__(16) __half g_wihc_h[G3 * D2];   // 12.6 MB (rows of 1024)
__device__ __align__(16) __half g_vr_h[D2 * D4];     //  4.2 MB (rows of 2048)
__device__ __align__(16) __half g_ur_h[D2 * D2];     //  2.1 MB (rows of 1024)
__device__ __align__(16) __half g_wa_h[D2 * D2];     //  2.1 MB (rows of 1024)

// ---------------- helpers ----------------
__device__ __forceinline__ float wred(float v) {
#pragma unroll
    for (int o = 16; o; o >>= 1) v += __shfl_xor_sync(0xffffffffu, v, o);
    return v;
}

__device__ __forceinline__ void wred2(float& a, float& b) {
#pragma unroll
    for (int o = 16; o; o >>= 1) {
        float ta = __shfl_xor_sync(0xffffffffu, a, o);
        float tb = __shfl_xor_sync(0xffffffffu, b, o);
        a += ta; b += tb;
    }
}
__device__ __forceinline__ void wred3(float& a, float& b, float& c) {
#pragma unroll
    for (int o = 16; o; o >>= 1) {
        float ta = __shfl_xor_sync(0xffffffffu, a, o);
        float tb = __shfl_xor_sync(0xffffffffu, b, o);
        float tc = __shfl_xor_sync(0xffffffffu, c, o);
        a += ta; b += tb; c += tc;
    }
}

template <int LEN>
__device__ __forceinline__ float warp_dot(const float* __restrict__ w,
                                          const float* __restrict__ v, int lane) {
    constexpr int NI = LEN / 128;
    float acc = 0.f;
#pragma unroll
    for (int i = 0; i < NI; ++i) {
        float4 a = *reinterpret_cast<const float4*>(w + i * 128 + lane * 4);
        float4 b = *reinterpret_cast<const float4*>(v + i * 128 + lane * 4);
        acc = fmaf(a.x, b.x, acc); acc = fmaf(a.y, b.y, acc);
        acc = fmaf(a.z, b.z, acc); acc = fmaf(a.w, b.w, acc);
    }
    return wred(acc);
}

// Replay-safe generation grid barrier.
__device__ __forceinline__ void gsync(unsigned gen) {
    __syncthreads();
    if (threadIdx.x == 0) {
        __threadfence();
        unsigned prev = atomicAdd(&g_bar_cnt, 1u);
        if (prev == NB - 1u) {
            g_bar_cnt = 0u;
            __threadfence();
            *(volatile unsigned*)&g_bar_gen = gen;
        } else {
            while ((int)(*(volatile unsigned*)&g_bar_gen - gen) < 0) __nanosleep(32);
            __threadfence();
        }
    }
    __syncthreads();
}

// packed fp32x2 FMA (Blackwell FFMA2 — only reachable via PTX)
#define FMA2(c, a, b) \
    asm("fma.rn.f32x2 %0, %1, %2, %0;" : "+l"(c) : "l"(a), "l"(b))

// fma of 8 fp16 weights (as uint4) against two float4 operand slices
#define FMA_H8(raw, va, vb, acc0, acc1) do {                                   \
    const __half2* _hp = reinterpret_cast<const __half2*>(&(raw));             \
    float2 _w0 = __half22float2(_hp[0]); float2 _w1 = __half22float2(_hp[1]);  \
    float2 _w2 = __half22float2(_hp[2]); float2 _w3 = __half22float2(_hp[3]);  \
    acc0 = fmaf(_w0.x, (va).x, acc0); acc0 = fmaf(_w0.y, (va).y, acc0);        \
    acc0 = fmaf(_w1.x, (va).z, acc0); acc0 = fmaf(_w1.y, (va).w, acc0);        \
    acc1 = fmaf(_w2.x, (vb).x, acc1); acc1 = fmaf(_w2.y, (vb).y, acc1);        \
    acc1 = fmaf(_w3.x, (vb).z, acc1); acc1 = fmaf(_w3.y, (vb).w, acc1);        \
} while (0)

// ---------------- permuted weight conversion ----------------
__device__ __forceinline__ uint4 pack8(float4 a, float4 b) {
    __half2 h0 = __floats2half2_rn(a.x, a.y);
    __half2 h1 = __floats2half2_rn(a.z, a.w);
    __half2 h2 = __floats2half2_rn(b.x, b.y);
    __half2 h3 = __floats2half2_rn(b.z, b.w);
    uint4 o;
    o.x = reinterpret_cast<unsigned&>(h0);
    o.y = reinterpret_cast<unsigned&>(h1);
    o.z = reinterpret_cast<unsigned&>(h2);
    o.w = reinterpret_cast<unsigned&>(h3);
    return o;
}

// rows of length 2048: W_hh (G3 rows) then v_r (D2 rows)
__global__ void k_convp2048(const float* __restrict__ whh, const float* __restrict__ vr) {
    int idx = blockIdx.x * blockDim.x + threadIdx.x;   // over (G3+D2)*256
    if (idx >= (G3 + D2) * 256) return;
    int row = idx >> 8, s = idx & 255;
    int i = s >> 5, l = s & 31;
    const float* src; __half* dst;
    if (row < G3) { src = whh + (size_t)row * D4;        dst = g_whh_h + (size_t)row * D4; }
    else          { src = vr  + (size_t)(row - G3) * D4; dst = g_vr_h + (size_t)(row - G3) * D4; }
    float4 a = *reinterpret_cast<const float4*>(src + i * 256 + l * 4);
    float4 b = *reinterpret_cast<const float4*>(src + i * 256 + 128 + l * 4);
    reinterpret_cast<uint4*>(dst)[s] = pack8(a, b);
}

// rows of length 1024: W_ih c-half (G3 rows, strided src), u_r (D2), w_a (D2)
__global__ void k_convp1024(const float* __restrict__ w_ih, const float* __restrict__ ur,
                            const float* __restrict__ wa) {
    int idx = blockIdx.x * blockDim.x + threadIdx.x;   // over (G3+2*D2)*128
    if (idx >= (G3 + 2 * D2) * 128) return;
    int row = idx >> 7, s = idx & 127;
    int i = s >> 5, l = s & 31;
    const float* src; __half* dst;
    if (row < G3)           { src = w_ih + (size_t)row * D4 + D2;         dst = g_wihc_h + (size_t)row * D2; }
    else if (row < G3 + D2) { src = ur + (size_t)(row - G3) * D2;         dst = g_ur_h + (size_t)(row - G3) * D2; }
    else                    { src = wa + (size_t)(row - G3 - D2) * D2;    dst = g_wa_h + (size_t)(row - G3 - D2) * D2; }
    float4 a = *reinterpret_cast<const float4*>(src + i * 256 + l * 4);
    float4 b = *reinterpret_cast<const float4*>(src + i * 256 + 128 + l * 4);
    reinterpret_cast<uint4*>(dst)[s] = pack8(a, b);
}

// ---------------- setup kernels ----------------
__global__ void k_colsum(const float* __restrict__ h_q, const float* __restrict__ h_p) {
    int b = blockIdx.x;
    int r0 = b * 65, r1 = min(r0 + 65, NSUM);
    int c = threadIdx.x;
    float acc[4] = {0.f, 0.f, 0.f, 0.f};
    for (int r = r0; r < r1; ++r) {
        const float* src = (r < NQ) ? (h_q + (size_t)r * D2) : (h_p + (size_t)(r - NQ) * D2);
#pragma unroll
        for (int i = 0; i < 4; ++i) acc[i] += src[c + i * 256];
    }
#pragma unroll
    for (int i = 0; i < 4; ++i) g_hpart[b * D2 + c + i * 256] = acc[i];
}

__global__ void k_finish_h() {
    int c = blockIdx.x * 256 + threadIdx.x;
    float s = 0.f;
#pragma unroll
    for (int b = 0; b < 64; ++b) s += g_hpart[b * D2 + c];
    g_h[c] = s;
}

__global__ void k_rows(const float* __restrict__ u_a, const float* __restrict__ w_d,
                       const float* __restrict__ w_d_b,
                       const float* __restrict__ h_q, const float* __restrict__ h_p) {
    int warp = threadIdx.x >> 5, lane = threadIdx.x & 31;
    int row = blockIdx.x * 8 + warp;
    if (row < D2) {
        float dot = warp_dot<D2>(u_a + (size_t)row * D2, g_h, lane);
        if (lane == 0) g_uah[row] = dot;
    } else if (row < 2 * D2) {
        int j = row - D2;
        float dot = warp_dot<D2>(w_d + (size_t)j * D2, h_q, lane);
        if (lane == 0) g_d[0][j] = tanhf(dot + w_d_b[j]);
    } else {
        int j = row - 2 * D2;
        float dot = warp_dot<D2>(w_d + (size_t)j * D2, h_p, lane);
        if (lane == 0) g_d[0][D2 + j] = tanhf(dot + w_d_b[j]);
    }
}

// GIw[t][r] = W_ih[r, :D2] @ ans[t] + b_ih[r]  (rows 0..6143)
// RW [t][j] = w_r[j] @ ans[t]                  (rows 6144..7167)
__global__ void __launch_bounds__(256) k_gemm0(
    const float* __restrict__ w_ih, const float* __restrict__ w_r,
    const float* __restrict__ b_ih, const float* __restrict__ ans) {
    __shared__ __align__(16) float Wt[32][68];
    __shared__ __align__(16) float At[32][68];
    int rbase = blockIdx.x * 64;
    int tid = threadIdx.x;
    int rr = tid & 15, tt = tid >> 4;
    float acc[4][4];
#pragma unroll
    for (int i = 0; i < 4; ++i)
#pragma unroll
        for (int j = 0; j < 4; ++j) acc[i][j] = 0.f;

    float4 wv[2], av[2];
#pragma unroll
    for (int it = 0; it < 2; ++it) {
        int i = tid + it * 256;
        int r = i >> 3, k4 = (i & 7) * 4;
        int row = rbase + r;
        const float* src = (row < G3) ? (w_ih + (size_t)row * D4)
                                      : (w_r + (size_t)(row - G3) * D2);
        wv[it] = *reinterpret_cast<const float4*>(src + k4);
        av[it] = *reinterpret_cast<const float4*>(ans + (size_t)r * D2 + k4);
    }

    for (int k0 = 0; k0 < D2; k0 += 32) {
        __syncthreads();
#pragma unroll
        for (int it = 0; it < 2; ++it) {
            int i = tid + it * 256;
            int r = i >> 3, k4 = (i & 7) * 4;
            Wt[k4 + 0][r] = wv[it].x; Wt[k4 + 1][r] = wv[it].y;
            Wt[k4 + 2][r] = wv[it].z; Wt[k4 + 3][r] = wv[it].w;
            At[k4 + 0][r] = av[it].x; At[k4 + 1][r] = av[it].y;
            At[k4 + 2][r] = av[it].z; At[k4 + 3][r] = av[it].w;
        }
        __syncthreads();
        int kn = k0 + 32;
        if (kn < D2) {
#pragma unroll
            for (int it = 0; it < 2; ++it) {
                int i = tid + it * 256;
                int r = i >> 3, k4 = (i & 7) * 4;
                int row = rbase + r;
                const float* src = (row < G3) ? (w_ih + (size_t)row * D4)
                                              : (w_r + (size_t)(row - G3) * D2);
                wv[it] = *reinterpret_cast<const float4*>(src + kn + k4);
                av[it] = *reinterpret_cast<const float4*>(ans + (size_t)r * D2 + kn + k4);
            }
        }
#pragma unroll
        for (int k = 0; k < 32; ++k) {
            float4 wv_ = *reinterpret_cast<const float4*>(&Wt[k][rr * 4]);
            float4 av_ = *reinterpret_cast<const float4*>(&At[k][tt * 4]);
            float wa[4] = {wv_.x, wv_.y, wv_.z, wv_.w};
            float aa[4] = {av_.x, av_.y, av_.z, av_.w};
#pragma unroll
            for (int i = 0; i < 4; ++i)
#pragma unroll
                for (int j = 0; j < 4; ++j)
                    acc[i][j] = fmaf(wa[i], aa[j], acc[i][j]);
        }
    }
#pragma unroll
    for (int i = 0; i < 4; ++i) {
        int row = rbase + rr * 4 + i;
        float b = (row < G3) ? b_ih[row] : 0.f;
#pragma unroll
        for (int j = 0; j < 4; ++j) {
            int t = tt * 4 + j;
            float v = acc[i][j] + b;
            if (row < G3) g_GIw[(size_t)t * G3 + row] = v;
            else          g_RW[(size_t)t * D2 + (row - G3)] = v;
        }
    }
}

// ---------------- persistent recurrence kernel (fp16, smem operands, occ 2) -
__global__ void __launch_bounds__(NT, 2) k_persist(
    const float* __restrict__ v_w, const float* __restrict__ b_hh) {
    const int tid = threadIdx.x;
    const int wid = tid >> 5, lane = tid & 31;
    const int gw = blockIdx.x * NWARP + wid;
    __shared__ __align__(16) float sh_h[D4];   // hprev (8KB)
    __shared__ __align__(16) float sh_c[D2];   // context c (4KB)
    __shared__ float sred0[NT];
    __shared__ float sred1[NT];
    __shared__ float s_a[2];
    __shared__ unsigned s_gen;

    if (tid == 0) s_gen = *(volatile unsigned*)&g_bar_gen;
    __syncthreads();
    unsigned gen = s_gen;

    const float4* h4 = reinterpret_cast<const float4*>(sh_h);   // 512 float4
    const float4* c4 = reinterpret_cast<const float4*>(sh_c);   // 256 float4
    float4* c4w = reinterpret_cast<float4*>(sh_c);

    for (int t = 0; t < LL; ++t) {
        const int cur = t & 1, nxt = cur ^ 1;
        {
            const float4* src = reinterpret_cast<const float4*>(g_d[cur]);
            float4* dst = reinterpret_cast<float4*>(sh_h);
            dst[tid] = src[tid];
            dst[tid + 256] = src[tid + 256];
        }
        __syncthreads();

        // ---------------- phase A ----------------
        // ids: [0,3072) W_hh row pairs | [3072,3584) v_r row pairs
        //      [3584,4608) attention rows (both d-rows)
        for (int id = gw; id < 4608; id += GWARPS) {
            if (id < 3072) {
                int r = id * 2;
                const uint4* W0 = reinterpret_cast<const uint4*>(g_whh_h + (size_t)r * D4) + lane;
                const uint4* W1 = W0 + (D4 / 8);
                float a0 = 0.f, a1 = 0.f, b0 = 0.f, b1 = 0.f;
#pragma unroll
                for (int i = 0; i < 8; ++i) {
                    uint4 r0 = W0[i * 32];
                    uint4 r1 = W1[i * 32];
                    float4 va = h4[i * 64 + lane];
                    float4 vb = h4[i * 64 + 32 + lane];
                    FMA_H8(r0, va, vb, a0, a1);
                    FMA_H8(r1, va, vb, b0, b1);
                }
                float da = a0 + a1, db = b0 + b1;
                wred2(da, db);
                if (lane == 0) {
                    g_gh[r]     = da + b_hh[r];
                    g_gh[r + 1] = db + b_hh[r + 1];
                }
            } else if (id < 3584) {
                int j = (id - 3072) * 2;
                const uint4* W0 = reinterpret_cast<const uint4*>(g_vr_h + (size_t)j * D4) + lane;
                const uint4* W1 = W0 + (D4 / 8);
                float a0 = 0.f, a1 = 0.f, b0 = 0.f, b1 = 0.f;
#pragma unroll
                for (int i = 0; i < 8; ++i) {
                    uint4 r0 = W0[i * 32];
                    uint4 r1 = W1[i * 32];
                    float4 va = h4[i * 64 + lane];
                    float4 vb = h4[i * 64 + 32 + lane];
                    FMA_H8(r0, va, vb, a0, a1);
                    FMA_H8(r1, va, vb, b0, b1);
                }
                float da = a0 + a1, db = b0 + b1;
                wred2(da, db);
                if (lane == 0) { g_vt[j] = da; g_vt[j + 1] = db; }
            } else {
                int j = id - 3584;
                const uint4* W4 = reinterpret_cast<const uint4*>(g_wa_h + (size_t)j * D2) + lane;
                float s0a = 0.f, s0b = 0.f, s1a = 0.f, s1b = 0.f;
#pragma unroll
                for (int i = 0; i < 4; ++i) {
                    uint4 raw = W4[i * 32];
                    float4 va0 = h4[i * 64 + lane];
                    float4 vb0 = h4[i * 64 + 32 + lane];
                    float4 va1 = h4[256 + i * 64 + lane];
                    float4 vb1 = h4[256 + i * 64 + 32 + lane];
                    FMA_H8(raw, va0, vb0, s0a, s0b);
                    FMA_H8(raw, va1, vb1, s1a, s1b);
                }
                float a0 = s0a + s0b, a1 = s1a + s1b;
                wred2(a0, a1);
                if (lane == 0) {
                    float vj = v_w[j], uj = g_uah[j];
                    g_scon[j]      = vj * tanhf(a0 + uj);
                    g_scon[D2 + j] = vj * tanhf(a1 + uj);
                }
            }
        }
        ++gen; gsync(gen);

        // ---------------- phase B preamble: scores -> a -> c (smem) ----
        {
            float p0 = 0.f, p1 = 0.f;
#pragma unroll
            for (int kk = 0; kk < 4; ++kk) {
                p0 += g_scon[tid + kk * 256];
                p1 += g_scon[D2 + tid + kk * 256];
            }
            sred0[tid] = p0; sred1[tid] = p1;
            __syncthreads();
            for (int s = 128; s; s >>= 1) {
                if (tid < s) { sred0[tid] += sred0[tid + s]; sred1[tid] += sred1[tid + s]; }
                __syncthreads();
            }
            if (tid == 0) {
                float s0 = sred0[0], s1 = sred1[0];
                float m = fmaxf(s0, s1);
                float e0 = expf(s0 - m), e1 = expf(s1 - m);
                float inv = 1.f / (e0 + e1);
                s_a[0] = e0 * inv; s_a[1] = e1 * inv;
            }
            __syncthreads();
            float a0 = s_a[0], a1 = s_a[1];
            float4 lo = h4[tid], hi = h4[256 + tid];
            float4 cv;
            cv.x = a0 * lo.x + a1 * hi.x;
            cv.y = a0 * lo.y + a1 * hi.y;
            cv.z = a0 * lo.z + a1 * hi.z;
            cv.w = a0 * lo.w + a1 * hi.w;
            c4w[tid] = cv;
            __syncthreads();
        }

        // ---------------- phase B ----------------
        // ids: [0,2048) GRU lane k | [2048,3072) u_r rows | [3072,3088) maxout
        for (int id = gw; id < 3088; id += GWARPS) {
            if (id < D4) {
                int k = id;
                const uint4* Wr4 = reinterpret_cast<const uint4*>(g_wihc_h + (size_t)k * D2) + lane;
                const uint4* Wz4 = reinterpret_cast<const uint4*>(g_wihc_h + (size_t)(k + D4) * D2) + lane;
                const uint4* Wn4 = reinterpret_cast<const uint4*>(g_wihc_h + (size_t)(k + 2 * D4) * D2) + lane;
                float ar0 = 0.f, ar1 = 0.f, az0 = 0.f, az1 = 0.f, an0 = 0.f, an1 = 0.f;
#pragma unroll
                for (int i = 0; i < 4; ++i) {
                    uint4 rr_ = Wr4[i * 32];
                    uint4 rz_ = Wz4[i * 32];
                    uint4 rn_ = Wn4[i * 32];
                    float4 va = c4[i * 64 + lane];
                    float4 vb = c4[i * 64 + 32 + lane];
                    FMA_H8(rr_, va, vb, ar0, ar1);
                    FMA_H8(rz_, va, vb, az0, az1);
                    FMA_H8(rn_, va, vb, an0, an1);
                }
                float ar = ar0 + ar1, az = az0 + az1, an = an0 + an1;
                wred3(ar, az, an);
                if (lane == 0) {
                    const float* gi = g_GIw + (size_t)t * G3;
                    float rg = 1.f / (1.f + expf(-(gi[k]          + ar + g_gh[k])));
                    float zg = 1.f / (1.f + expf(-(gi[k + D4]     + az + g_gh[k + D4])));
                    float ng = tanhf(gi[k + 2 * D4] + an + rg * g_gh[k + 2 * D4]);
                    g_d[nxt][k] = (1.f - zg) * ng + zg * sh_h[k];
                }
            } else if (id < 3072) {
                int j = id - D4;
                const uint4* W4 = reinterpret_cast<const uint4*>(g_ur_h + (size_t)j * D2) + lane;
                float a0 = 0.f, a1 = 0.f;
#pragma unroll
                for (int i = 0; i < 4; ++i) {
                    uint4 raw = W4[i * 32];
                    float4 va = c4[i * 64 + lane];
                    float4 vb = c4[i * 64 + 32 + lane];
                    FMA_H8(raw, va, vb, a0, a1);
                }
                float dot = wred(a0 + a1);
                if (lane == 0)
                    g_rpart[cur][j] = g_RW[(size_t)t * D2 + j] + dot;
            } else {
                if (t > 0) {
                    int j = (id - 3072) * 32 + lane;
                    float f0 = g_rpart[nxt][j]      + g_vt[j];
                    float f1 = g_rpart[nxt][j + HH] + g_vt[j + HH];
                    g_rt[(size_t)(t - 1) * HH + j] = fmaxf(f0, f1);
                }
            }
        }
        ++gen; gsync(gen);
    }

    // ---------------- epilogue: finalize r_t for t=63 (h_new in g_d[0]) ----
    {
        const float4* src = reinterpret_cast<const float4*>(g_d[0]);
        float4* dst = reinterpret_cast<float4*>(sh_h);
        dst[tid] = src[tid];
        dst[tid + 256] = src[tid + 256];
        __syncthreads();
        for (int id = gw; id < 512; id += GWARPS) {
            int j = id * 2;
            const uint4* W0 = reinterpret_cast<const uint4*>(g_vr_h + (size_t)j * D4) + lane;
            const uint4* W1 = W0 + (D4 / 8);
            float a0 = 0.f, a1 = 0.f, b0 = 0.f, b1 = 0.f;
#pragma unroll
            for (int i = 0; i < 8; ++i) {
                uint4 r0 = W0[i * 32];
                uint4 r1 = W1[i * 32];
                float4 va = h4[i * 64 + lane];
                float4 vb = h4[i * 64 + 32 + lane];
                FMA_H8(r0, va, vb, a0, a1);
                FMA_H8(r1, va, vb, b0, b1);
            }
            float da = a0 + a1, db = b0 + b1;
            wred2(da, db);
            if (lane == 0) { g_vt[j] = da; g_vt[j + 1] = db; }
        }
        ++gen; gsync(gen);
        if (gw < 16) {                 // t=63 wrote g_rpart[1]
            int j = gw * 32 + lane;
            float f0 = g_rpart[1][j]      + g_vt[j];
            float f1 = g_rpart[1][j + HH] + g_vt[j + HH];
            g_rt[(size_t)63 * HH + j] = fmaxf(f0, f1);
        }
    }
}

// ---------------- logits GEMM: (64 x 512) @ wo^T (512 x 32000), FFMA2 ------
__global__ void __launch_bounds__(256) k_logits(const float* __restrict__ wo) {
    __shared__ __align__(16) float At2[32][144];  // At2[k][2m] = At2[k][2m+1] = A[m][k]
    __shared__ __align__(16) float Bt[32][136];   // Bt[k][n]
    const int tid = threadIdx.x;
    const int v0 = blockIdx.x * 128;              // 250 blocks
    const int tm = tid & 15, tn = tid >> 4;
    unsigned long long acc[4][4];
#pragma unroll
    for (int i = 0; i < 4; ++i)
#pragma unroll
        for (int j = 0; j < 4; ++j) acc[i][j] = 0ull;

    for (int k0 = 0; k0 < HH; k0 += 32) {
        __syncthreads();
#pragma unroll
        for (int it = 0; it < 2; ++it) {
            int i = tid + it * 256;
            int m = i >> 3, k4 = (i & 7) * 4;
            float4 v = *reinterpret_cast<const float4*>(g_rt + (size_t)m * HH + k0 + k4);
            At2[k4 + 0][2 * m] = v.x; At2[k4 + 0][2 * m + 1] = v.x;
            At2[k4 + 1][2 * m] = v.y; At2[k4 + 1][2 * m + 1] = v.y;
            At2[k4 + 2][2 * m] = v.z; At2[k4 + 2][2 * m + 1] = v.z;
            At2[k4 + 3][2 * m] = v.w; At2[k4 + 3][2 * m + 1] = v.w;
        }
#pragma unroll
        for (int it = 0; it < 4; ++it) {
            int i = tid + it * 256;
            int n = i >> 3, k4 = (i & 7) * 4;
            float4 v = *reinterpret_cast<const float4*>(wo + (size_t)(v0 + n) * HH + k0 + k4);
            Bt[k4 + 0][n] = v.x; Bt[k4 + 1][n] = v.y;
            Bt[k4 + 2][n] = v.z; Bt[k4 + 3][n] = v.w;
        }
        __syncthreads();
#pragma unroll
        for (int k = 0; k < 32; ++k) {
            ulonglong2 aA = *reinterpret_cast<const ulonglong2*>(&At2[k][tm * 8]);
            ulonglong2 aB = *reinterpret_cast<const ulonglong2*>(&At2[k][tm * 8 + 4]);
            ulonglong2 b0 = *reinterpret_cast<const ulonglong2*>(&Bt[k][tn * 8]);
            ulonglong2 b1 = *reinterpret_cast<const ulonglong2*>(&Bt[k][tn * 8 + 4]);
            FMA2(acc[0][0], aA.x, b0.x); FMA2(acc[0][1], aA.x, b0.y);
            FMA2(acc[0][2], aA.x, b1.x); FMA2(acc[0][3], aA.x, b1.y);
            FMA2(acc[1][0], aA.y, b0.x); FMA2(acc[1][1], aA.y, b0.y);
            FMA2(acc[1][2], aA.y, b1.x); FMA2(acc[1][3], aA.y, b1.y);
            FMA2(acc[2][0], aB.x, b0.x); FMA2(acc[2][1], aB.x, b0.y);
            FMA2(acc[2][2], aB.x, b1.x); FMA2(acc[2][3], aB.x, b1.y);
            FMA2(acc[3][0], aB.y, b0.x); FMA2(acc[3][1], aB.y, b0.y);
            FMA2(acc[3][2], aB.y, b1.x); FMA2(acc[3][3], aB.y, b1.y);
        }
    }
#pragma unroll
    for (int i = 0; i < 4; ++i) {
        float lo[4], hi[4];
#pragma unroll
        for (int j = 0; j < 4; ++j)
            asm("mov.b64 {%0, %1}, %2;" : "=f"(lo[j]), "=f"(hi[j]) : "l"(acc[i][j]));
        float* dst = g_logits + (size_t)(tm * 4 + i) * VV + v0 + tn * 8;
        *reinterpret_cast<float4*>(dst)     = make_float4(lo[0], hi[0], lo[1], hi[1]);
        *reinterpret_cast<float4*>(dst + 4) = make_float4(lo[2], hi[2], lo[3], hi[3]);
    }
}

// ---------------- row softmax over vocab -> d_out ----------------
__global__ void __launch_bounds__(512) k_softmax(float* __restrict__ out) {
    __shared__ float sh[512];
    const int row = blockIdx.x, tid = threadIdx.x;
    const float* lg = g_logits + (size_t)row * VV;
    float m = -INFINITY;
    for (int i = tid; i < VV; i += 512) m = fmaxf(m, lg[i]);
    sh[tid] = m; __syncthreads();
    for (int s = 256; s; s >>= 1) { if (tid < s) sh[tid] = fmaxf(sh[tid], sh[tid + s]); __syncthreads(); }
    m = sh[0]; __syncthreads();
    float sum = 0.f;
    for (int i = tid; i < VV; i += 512) sum += expf(lg[i] - m);
    sh[tid] = sum; __syncthreads();
    for (int s = 256; s; s >>= 1) { if (tid < s) sh[tid] += sh[tid + s]; __syncthreads(); }
    float inv = 1.f / sh[0];
    float* o = out + (size_t)row * VV;
    for (int i = tid; i < VV; i += 512) o[i] = expf(lg[i] - m) * inv;
}

// ---------------- launch ----------------
extern "C" void kernel_launch(void* const* d_in, const int* in_sizes, int n_in,
                              void* d_out, int out_size) {
    (void)in_sizes; (void)n_in; (void)out_size;
    const float* h_q    = (const float*)d_in[0];
    const float* h_p    = (const float*)d_in[1];
    const float* ans    = (const float*)d_in[2];
    const float* v_w    = (const float*)d_in[3];
    const float* w_d_w  = (const float*)d_in[4];
    const float* w_d_b  = (const float*)d_in[5];
    const float* w_a_w  = (const float*)d_in[6];
    const float* u_a_w  = (const float*)d_in[7];
    const float* w_r_w  = (const float*)d_in[8];
    const float* u_r_w  = (const float*)d_in[9];
    const float* v_r_w  = (const float*)d_in[10];
    const float* w_o_w  = (const float*)d_in[11];
    const float* gw_ih  = (const float*)d_in[12];
    const float* gw_hh  = (const float*)d_in[13];
    const float* gb_ih  = (const float*)d_in[14];
    const float* gb_hh  = (const float*)d_in[15];
    float* out = (float*)d_out;

    // permuted fp16 weight conversion (one-time per launch)
    k_convp2048<<<(G3 + D2) * 256 / 256, 256>>>(gw_hh, v_r_w);
    k_convp1024<<<(G3 + 2 * D2) * 128 / 256, 256>>>(gw_ih, u_r_w, w_a_w);

    k_colsum<<<64, 256>>>(h_q, h_p);
    k_finish_h<<<4, 256>>>();
    k_rows<<<384, 256>>>(u_a_w, w_d_w, w_d_b, h_q, h_p);
    k_gemm0<<<112, 256>>>(gw_ih, w_r_w, gb_ih, ans);
    k_persist<<<NB, NT>>>(v_w, gb_hh);
    k_logits<<<VV / 128, 256>>>(w_o_w);
    k_softmax<<<LL, 512>>>(out);
}